// round 2
// baseline (speedup 1.0000x reference)
#include <cuda_runtime.h>
#include <cuda_bf16.h>
#include <math_constants.h>

// Problem constants
#define BATCH 4
#define SEQ   2048
#define DIM   1024
#define HEADS 16
#define HD    64
#define NROWS (BATCH * SEQ)   // 8192
#define QK_SCALE 0.125f        // 64^-0.5

// ---------------------------------------------------------------------------
// Scratch (device globals; no allocations allowed)
// ---------------------------------------------------------------------------
__device__ float g_Q[BATCH * HEADS * SEQ * HD];  // [B,H,S,Hd], pre-scaled by QK_SCALE
__device__ float g_K[BATCH * HEADS * SEQ * HD];
__device__ float g_V[BATCH * HEADS * SEQ * HD];
__device__ float g_O[NROWS * DIM];               // attention out, [B*S, D] row-major

// ---------------------------------------------------------------------------
// GEMM: C[n,m] = sum_k A[n,k] * W[m,k] + bias[m]   (NT, both row-major, K contig)
// 128x128 tile, BK=8, 256 threads, 8x8 per thread.
// mode 0: write to [B,H,S,Hd] layout, value *= scale (after bias)
// mode 1: write row-major C[n*Mcols+m]
// ---------------------------------------------------------------------------
#define GBM 128
#define GBN 128
#define GBK 8
#define SMPAD 132

__global__ __launch_bounds__(256)
void gemm_nt_kernel(const float* __restrict__ A,
                    const float* __restrict__ W,
                    const float* __restrict__ bias,
                    float* __restrict__ C,
                    int Kdim, int Mcols,
                    int mode, float scale)
{
    __shared__ float As[GBK][SMPAD];
    __shared__ float Ws[GBK][SMPAD];

    const int tid = threadIdx.x;
    const int tx = tid & 15;        // 0..15
    const int ty = tid >> 4;        // 0..15
    const int row0 = blockIdx.y * GBM;
    const int col0 = blockIdx.x * GBN;

    // cooperative load indices: each thread loads one float4 of A and of W per step
    const int lr = tid >> 1;              // 0..127 (row within tile)
    const int lk = (tid & 1) * 4;         // 0 or 4

    const float* Aptr = A + (size_t)(row0 + lr) * Kdim + lk;
    const float* Wptr = W + (size_t)(col0 + lr) * Kdim + lk;

    float acc[8][8];
#pragma unroll
    for (int i = 0; i < 8; i++)
#pragma unroll
        for (int j = 0; j < 8; j++) acc[i][j] = 0.f;

    for (int k0 = 0; k0 < Kdim; k0 += GBK) {
        float4 a = *(const float4*)(Aptr + k0);
        float4 w = *(const float4*)(Wptr + k0);
        As[lk + 0][lr] = a.x; As[lk + 1][lr] = a.y;
        As[lk + 2][lr] = a.z; As[lk + 3][lr] = a.w;
        Ws[lk + 0][lr] = w.x; Ws[lk + 1][lr] = w.y;
        Ws[lk + 2][lr] = w.z; Ws[lk + 3][lr] = w.w;
        __syncthreads();

#pragma unroll
        for (int kk = 0; kk < GBK; kk++) {
            float4 a0 = *(const float4*)&As[kk][ty * 8];
            float4 a1 = *(const float4*)&As[kk][ty * 8 + 4];
            float4 w0 = *(const float4*)&Ws[kk][tx * 8];
            float4 w1 = *(const float4*)&Ws[kk][tx * 8 + 4];
            float av[8] = {a0.x, a0.y, a0.z, a0.w, a1.x, a1.y, a1.z, a1.w};
            float wv[8] = {w0.x, w0.y, w0.z, w0.w, w1.x, w1.y, w1.z, w1.w};
#pragma unroll
            for (int i = 0; i < 8; i++)
#pragma unroll
                for (int j = 0; j < 8; j++)
                    acc[i][j] = fmaf(av[i], wv[j], acc[i][j]);
        }
        __syncthreads();
    }

    // epilogue
#pragma unroll
    for (int i = 0; i < 8; i++) {
        const int n = row0 + ty * 8 + i;
#pragma unroll
        for (int j = 0; j < 8; j++) {
            const int m = col0 + tx * 8 + j;
            float v = acc[i][j] + bias[m];
            if (mode == 0) {
                v *= scale;
                const int b = n >> 11;          // n / SEQ
                const int s = n & (SEQ - 1);
                const int h = m >> 6;           // m / HD
                const int hd = m & (HD - 1);
                C[(((size_t)(b * HEADS + h) * SEQ) + s) * HD + hd] = v;
            } else {
                C[(size_t)n * Mcols + m] = v;
            }
        }
    }
}

// ---------------------------------------------------------------------------
// Flash attention, fp32, online softmax. 1 thread = 1 query row.
// Block: 128 threads (128 query rows), grid: (SEQ/128, B*H).
// Q is pre-scaled by QK_SCALE. Masked keys are skipped (== score -inf).
// Output written to g_O in [B*S, D] row-major (head h occupies cols h*64..).
// ---------------------------------------------------------------------------
#define ATTN_ROWS 128
#define KTILE 64

__global__ __launch_bounds__(ATTN_ROWS)
void attn_kernel(const float* __restrict__ Q,
                 const float* __restrict__ Kmat,
                 const float* __restrict__ V,
                 const int* __restrict__ mask,
                 float* __restrict__ O)
{
    __shared__ float Ks[KTILE][HD];
    __shared__ float Vs[KTILE][HD];
    __shared__ int Ms[KTILE];

    const int tid = threadIdx.x;
    const int bh = blockIdx.y;        // 0..63
    const int b = bh >> 4;
    const int h = bh & 15;
    const int s = blockIdx.x * ATTN_ROWS + tid;

    const float* qrow = Q + ((size_t)bh * SEQ + s) * HD;
    float q[HD];
#pragma unroll
    for (int i = 0; i < HD / 4; i++) {
        float4 t = *(const float4*)(qrow + i * 4);
        q[i * 4 + 0] = t.x; q[i * 4 + 1] = t.y;
        q[i * 4 + 2] = t.z; q[i * 4 + 3] = t.w;
    }

    float acc[HD];
#pragma unroll
    for (int i = 0; i < HD; i++) acc[i] = 0.f;
    float mmax = -CUDART_INF_F;
    float l = 0.f;

    const float* Kbase = Kmat + (size_t)bh * SEQ * HD;
    const float* Vbase = V + (size_t)bh * SEQ * HD;
    const int* mrow = mask + b * SEQ;

    for (int k0 = 0; k0 < SEQ; k0 += KTILE) {
        __syncthreads();
        // load K/V tiles: 4096 floats each; 128 threads -> 8 float4 each
#pragma unroll
        for (int i = 0; i < 8; i++) {
            int idx = tid + i * ATTN_ROWS;    // float4 index 0..1023
            int r = idx >> 4;
            int c = (idx & 15) * 4;
            *(float4*)&Ks[r][c] = *(const float4*)(Kbase + (size_t)(k0 + r) * HD + c);
            *(float4*)&Vs[r][c] = *(const float4*)(Vbase + (size_t)(k0 + r) * HD + c);
        }
        if (tid < KTILE) Ms[tid] = mrow[k0 + tid];
        __syncthreads();

#pragma unroll 1
        for (int j = 0; j < KTILE; j++) {
            if (Ms[j]) continue;   // masked key: score = -inf -> zero contribution

            float dot = 0.f;
#pragma unroll
            for (int d4 = 0; d4 < HD / 4; d4++) {
                float4 kv = *(const float4*)&Ks[j][d4 * 4];
                dot = fmaf(q[d4 * 4 + 0], kv.x, dot);
                dot = fmaf(q[d4 * 4 + 1], kv.y, dot);
                dot = fmaf(q[d4 * 4 + 2], kv.z, dot);
                dot = fmaf(q[d4 * 4 + 3], kv.w, dot);
            }

            if (dot > mmax) {
                float corr = __expf(mmax - dot);  // exp(-inf)=0 handles first key
                l *= corr;
#pragma unroll
                for (int d = 0; d < HD; d++) acc[d] *= corr;
                mmax = dot;
            }
            float p = __expf(dot - mmax);
            l += p;
#pragma unroll
            for (int d4 = 0; d4 < HD / 4; d4++) {
                float4 vv = *(const float4*)&Vs[j][d4 * 4];
                acc[d4 * 4 + 0] = fmaf(p, vv.x, acc[d4 * 4 + 0]);
                acc[d4 * 4 + 1] = fmaf(p, vv.y, acc[d4 * 4 + 1]);
                acc[d4 * 4 + 2] = fmaf(p, vv.z, acc[d4 * 4 + 2]);
                acc[d4 * 4 + 3] = fmaf(p, vv.w, acc[d4 * 4 + 3]);
            }
        }
    }

    const float inv = 1.f / l;
    float* orow = O + ((size_t)(b * SEQ + s)) * DIM + h * HD;
#pragma unroll
    for (int i = 0; i < HD / 4; i++) {
        float4 t;
        t.x = acc[i * 4 + 0] * inv;
        t.y = acc[i * 4 + 1] * inv;
        t.z = acc[i * 4 + 2] * inv;
        t.w = acc[i * 4 + 3] * inv;
        *(float4*)(orow + i * 4) = t;
    }
}

// ---------------------------------------------------------------------------
// Launch
// ---------------------------------------------------------------------------
extern "C" void kernel_launch(void* const* d_in, const int* in_sizes, int n_in,
                              void* d_out, int out_size)
{
    const float* x  = (const float*)d_in[0];
    const int* mask = (const int*)d_in[1];   // bool promoted to int32 by harness
    const float* Wq = (const float*)d_in[2];
    const float* bq = (const float*)d_in[3];
    const float* Wk = (const float*)d_in[4];
    const float* bk = (const float*)d_in[5];
    const float* Wv = (const float*)d_in[6];
    const float* bv = (const float*)d_in[7];
    const float* Wo = (const float*)d_in[8];
    const float* bo = (const float*)d_in[9];
    float* out = (float*)d_out;

    float *pQ, *pK, *pV, *pO;
    cudaGetSymbolAddress((void**)&pQ, g_Q);
    cudaGetSymbolAddress((void**)&pK, g_K);
    cudaGetSymbolAddress((void**)&pV, g_V);
    cudaGetSymbolAddress((void**)&pO, g_O);

    dim3 ggrid(DIM / GBN, NROWS / GBM);   // (8, 64)
    gemm_nt_kernel<<<ggrid, 256>>>(x, Wq, bq, pQ, DIM, DIM, 0, QK_SCALE);
    gemm_nt_kernel<<<ggrid, 256>>>(x, Wk, bk, pK, DIM, DIM, 0, 1.0f);
    gemm_nt_kernel<<<ggrid, 256>>>(x, Wv, bv, pV, DIM, DIM, 0, 1.0f);

    dim3 agrid(SEQ / ATTN_ROWS, BATCH * HEADS);  // (16, 64)
    attn_kernel<<<agrid, ATTN_ROWS>>>(pQ, pK, pV, mask, pO);

    gemm_nt_kernel<<<ggrid, 256>>>(pO, Wo, bo, out, DIM, DIM, 1, 1.0f);
}

// round 4
// speedup vs baseline: 1.3961x; 1.3961x over previous
#include <cuda_runtime.h>
#include <cuda_bf16.h>
#include <math_constants.h>
#include <cstdint>

// Problem constants
#define BATCH 4
#define SEQ   2048
#define DIM   1024
#define HEADS 16
#define HD    64
#define NROWS (BATCH * SEQ)   // 8192
#define QK_SCALE 0.125f

__device__ __forceinline__ uint32_t smem_u32(const void* p) {
    uint32_t a;
    asm("{ .reg .u64 t; cvta.to.shared.u64 t, %1; cvt.u32.u64 %0, t; }" : "=r"(a) : "l"(p));
    return a;
}

__device__ __forceinline__ void mma16816(float* d, const uint32_t* a, const uint32_t* b) {
    asm volatile("mma.sync.aligned.m16n8k16.row.col.f32.bf16.bf16.f32 "
        "{%0,%1,%2,%3}, {%4,%5,%6,%7}, {%8,%9}, {%0,%1,%2,%3};"
        : "+f"(d[0]), "+f"(d[1]), "+f"(d[2]), "+f"(d[3])
        : "r"(a[0]), "r"(a[1]), "r"(a[2]), "r"(a[3]), "r"(b[0]), "r"(b[1]));
}

// ---------------------------------------------------------------------------
// Scratch (device globals)
// ---------------------------------------------------------------------------
__device__ float g_Q[BATCH * HEADS * SEQ * HD];
__device__ float g_K[BATCH * HEADS * SEQ * HD];
__device__ float g_V[BATCH * HEADS * SEQ * HD];
__device__ float g_O[NROWS * DIM];
__device__ __nv_bfloat16 g_xh[NROWS * DIM];
__device__ __nv_bfloat16 g_xl[NROWS * DIM];
__device__ __nv_bfloat16 g_wh[4 * DIM * DIM];
__device__ __nv_bfloat16 g_wl[4 * DIM * DIM];
__device__ __nv_bfloat16 g_oh[NROWS * DIM];
__device__ __nv_bfloat16 g_ol[NROWS * DIM];

// ---------------------------------------------------------------------------
// fp32 -> (bf16 hi, bf16 lo) split
// ---------------------------------------------------------------------------
struct bf4 { __nv_bfloat16 v[4]; };

__global__ void split_kernel(const float* __restrict__ src,
                             __nv_bfloat16* __restrict__ hi,
                             __nv_bfloat16* __restrict__ lo, int n4)
{
    for (int i = blockIdx.x * blockDim.x + threadIdx.x; i < n4; i += gridDim.x * blockDim.x) {
        float4 x = ((const float4*)src)[i];
        bf4 h, l;
        float f[4] = {x.x, x.y, x.z, x.w};
#pragma unroll
        for (int j = 0; j < 4; j++) {
            __nv_bfloat16 hv = __float2bfloat16(f[j]);
            h.v[j] = hv;
            l.v[j] = __float2bfloat16(f[j] - __bfloat162float(hv));
        }
        ((bf4*)hi)[i] = h;
        ((bf4*)lo)[i] = l;
    }
}

// ---------------------------------------------------------------------------
// bf16x3 GEMM via mma.sync.m16n8k16 (fp32 accum)
// C[n,m] = sum_k A[n,k]*W[m,k] + bias[m]   (NT, K contiguous both sides)
// CTA tile 128x128, BK=32 bf16, 8 warps (2 m x 4 n), warp tile 64x32.
// cp.async double-buffered. SMEM rows padded to 40 bf16 (80 B).
// mode 0: scatter to [B,H,S,Hd] * scale; mode 1: row-major [n*DIM+m]
// ---------------------------------------------------------------------------
#define BM 128
#define BN 128
#define BK 32
#define NKC (DIM / BK)            // 32
#define ROWPAD 40                 // bf16 per padded row (80 B)
#define TILE_SB (128 * ROWPAD * 2)  // 10240 B per operand tile
#define STAGE_SB (4 * TILE_SB)      // 40960 B
#define GEMM_SMEM (2 * STAGE_SB)    // 81920 B

__global__ __launch_bounds__(256, 1)
void gemm_mma(const __nv_bfloat16* __restrict__ Ahi, const __nv_bfloat16* __restrict__ Alo,
              const __nv_bfloat16* __restrict__ Whi, const __nv_bfloat16* __restrict__ Wlo,
              const float* __restrict__ bias, float* __restrict__ C,
              int mode, float scale)
{
    extern __shared__ char smraw[];
    const uint32_t smem_base = smem_u32(smraw);

    const int tid = threadIdx.x;
    const int lane = tid & 31;
    const int wid = tid >> 5;
    const int wm = wid & 1;        // 0..1
    const int wn = wid >> 1;       // 0..3
    const int row0 = blockIdx.y * BM;
    const int col0 = blockIdx.x * BN;

    const uint4* srcs[4] = {(const uint4*)Ahi, (const uint4*)Alo,
                            (const uint4*)Whi, (const uint4*)Wlo};
    const int bases[4] = {row0, row0, col0, col0};

    float acc[4][4][4];
#pragma unroll
    for (int i = 0; i < 4; i++)
#pragma unroll
        for (int j = 0; j < 4; j++)
#pragma unroll
            for (int r = 0; r < 4; r++) acc[i][j][r] = 0.f;

    // per-thread cp.async coordinates (2 uint4 per tile per stage)
    const int r0l = tid >> 2;                 // 0..63
    const int cu  = tid & 3;                  // uint4 col within 32-bf16 chunk

#define ISSUE_STAGE(kc, buf) do { \
    uint32_t sb_ = smem_base + (buf) * STAGE_SB; \
    _Pragma("unroll") \
    for (int t_ = 0; t_ < 4; t_++) { \
        _Pragma("unroll") \
        for (int j_ = 0; j_ < 2; j_++) { \
            int r_ = r0l + j_ * 64; \
            const uint4* g_ = srcs[t_] + (size_t)(bases[t_] + r_) * 128 + (kc) * 4 + cu; \
            uint32_t s_ = sb_ + t_ * TILE_SB + r_ * 80 + cu * 16; \
            asm volatile("cp.async.cg.shared.global [%0], [%1], 16;" :: "r"(s_), "l"(g_)); \
        } \
    } \
    asm volatile("cp.async.commit_group;" ::: "memory"); \
} while (0)

    ISSUE_STAGE(0, 0);

    for (int kc = 0; kc < NKC; kc++) {
        const int buf = kc & 1;
        if (kc + 1 < NKC) {
            ISSUE_STAGE(kc + 1, buf ^ 1);
            asm volatile("cp.async.wait_group 1;" ::: "memory");
        } else {
            asm volatile("cp.async.wait_group 0;" ::: "memory");
        }
        __syncthreads();

        const uint32_t sb = smem_base + buf * STAGE_SB;
#pragma unroll
        for (int s = 0; s < 2; s++) {
            uint32_t a_h[4][4], a_l[4][4];
            const uint32_t acol = s * 32 + ((lane >> 4) << 4);
#pragma unroll
            for (int mt = 0; mt < 4; mt++) {
                const int r = wm * 64 + mt * 16 + (lane & 15);
                uint32_t addr = sb + r * 80 + acol;
                asm volatile("ldmatrix.sync.aligned.m8n8.x4.shared.b16 {%0,%1,%2,%3}, [%4];"
                    : "=r"(a_h[mt][0]), "=r"(a_h[mt][1]), "=r"(a_h[mt][2]), "=r"(a_h[mt][3])
                    : "r"(addr));
                addr += TILE_SB;
                asm volatile("ldmatrix.sync.aligned.m8n8.x4.shared.b16 {%0,%1,%2,%3}, [%4];"
                    : "=r"(a_l[mt][0]), "=r"(a_l[mt][1]), "=r"(a_l[mt][2]), "=r"(a_l[mt][3])
                    : "r"(addr));
            }
            uint32_t b_h[4][2], b_l[4][2];
            const int mat = lane >> 3;
            const int mr = lane & 7;
            const uint32_t bcol = s * 32 + ((mat & 1) << 4);
#pragma unroll
            for (int np = 0; np < 2; np++) {
                const int n = wn * 32 + (np * 2 + (mat >> 1)) * 8 + mr;
                uint32_t addr = sb + 2 * TILE_SB + n * 80 + bcol;
                uint32_t q0, q1, q2, q3;
                asm volatile("ldmatrix.sync.aligned.m8n8.x4.shared.b16 {%0,%1,%2,%3}, [%4];"
                    : "=r"(q0), "=r"(q1), "=r"(q2), "=r"(q3) : "r"(addr));
                b_h[np * 2][0] = q0; b_h[np * 2][1] = q1;
                b_h[np * 2 + 1][0] = q2; b_h[np * 2 + 1][1] = q3;
                addr += TILE_SB;
                asm volatile("ldmatrix.sync.aligned.m8n8.x4.shared.b16 {%0,%1,%2,%3}, [%4];"
                    : "=r"(q0), "=r"(q1), "=r"(q2), "=r"(q3) : "r"(addr));
                b_l[np * 2][0] = q0; b_l[np * 2][1] = q1;
                b_l[np * 2 + 1][0] = q2; b_l[np * 2 + 1][1] = q3;
            }
#pragma unroll
            for (int mt = 0; mt < 4; mt++)
#pragma unroll
                for (int nt = 0; nt < 4; nt++) {
                    mma16816(acc[mt][nt], a_h[mt], b_h[nt]);
                    mma16816(acc[mt][nt], a_h[mt], b_l[nt]);
                    mma16816(acc[mt][nt], a_l[mt], b_h[nt]);
                }
        }
        __syncthreads();
    }

    // epilogue
    const int g = lane >> 2;
    const int tg2 = (lane & 3) * 2;
#pragma unroll
    for (int mt = 0; mt < 4; mt++) {
        const int rb = row0 + wm * 64 + mt * 16 + g;
#pragma unroll
        for (int nt = 0; nt < 4; nt++) {
            const int m = col0 + wn * 32 + nt * 8 + tg2;
            const float b0 = bias[m], b1 = bias[m + 1];
#pragma unroll
            for (int hh = 0; hh < 2; hh++) {
                const int n = rb + hh * 8;
                float v0 = acc[mt][nt][hh * 2 + 0] + b0;
                float v1 = acc[mt][nt][hh * 2 + 1] + b1;
                if (mode == 0) {
                    v0 *= scale; v1 *= scale;
                    const int b = n >> 11;
                    const int sq = n & (SEQ - 1);
                    const int h = m >> 6;
                    const int hd = m & (HD - 1);
                    float2 w; w.x = v0; w.y = v1;
                    *(float2*)&C[(((size_t)(b * HEADS + h) * SEQ) + sq) * HD + hd] = w;
                } else {
                    float2 w; w.x = v0; w.y = v1;
                    *(float2*)&C[(size_t)n * DIM + m] = w;
                }
            }
        }
    }
}

// ---------------------------------------------------------------------------
// Flash attention, fp32, online softmax (unchanged — passing R2 version)
// ---------------------------------------------------------------------------
#define ATTN_ROWS 128
#define KTILE 64

__global__ __launch_bounds__(ATTN_ROWS)
void attn_kernel(const float* __restrict__ Q,
                 const float* __restrict__ Kmat,
                 const float* __restrict__ V,
                 const int* __restrict__ mask,
                 float* __restrict__ O)
{
    __shared__ float Ks[KTILE][HD];
    __shared__ float Vs[KTILE][HD];
    __shared__ int Ms[KTILE];

    const int tid = threadIdx.x;
    const int bh = blockIdx.y;
    const int b = bh >> 4;
    const int h = bh & 15;
    const int s = blockIdx.x * ATTN_ROWS + tid;

    const float* qrow = Q + ((size_t)bh * SEQ + s) * HD;
    float q[HD];
#pragma unroll
    for (int i = 0; i < HD / 4; i++) {
        float4 t = *(const float4*)(qrow + i * 4);
        q[i * 4 + 0] = t.x; q[i * 4 + 1] = t.y;
        q[i * 4 + 2] = t.z; q[i * 4 + 3] = t.w;
    }

    float acc[HD];
#pragma unroll
    for (int i = 0; i < HD; i++) acc[i] = 0.f;
    float mmax = -CUDART_INF_F;
    float l = 0.f;

    const float* Kbase = Kmat + (size_t)bh * SEQ * HD;
    const float* Vbase = V + (size_t)bh * SEQ * HD;
    const int* mrow = mask + b * SEQ;

    for (int k0 = 0; k0 < SEQ; k0 += KTILE) {
        __syncthreads();
#pragma unroll
        for (int i = 0; i < 8; i++) {
            int idx = tid + i * ATTN_ROWS;
            int r = idx >> 4;
            int c = (idx & 15) * 4;
            *(float4*)&Ks[r][c] = *(const float4*)(Kbase + (size_t)(k0 + r) * HD + c);
            *(float4*)&Vs[r][c] = *(const float4*)(Vbase + (size_t)(k0 + r) * HD + c);
        }
        if (tid < KTILE) Ms[tid] = mrow[k0 + tid];
        __syncthreads();

#pragma unroll 1
        for (int j = 0; j < KTILE; j++) {
            if (Ms[j]) continue;

            float dot = 0.f;
#pragma unroll
            for (int d4 = 0; d4 < HD / 4; d4++) {
                float4 kv = *(const float4*)&Ks[j][d4 * 4];
                dot = fmaf(q[d4 * 4 + 0], kv.x, dot);
                dot = fmaf(q[d4 * 4 + 1], kv.y, dot);
                dot = fmaf(q[d4 * 4 + 2], kv.z, dot);
                dot = fmaf(q[d4 * 4 + 3], kv.w, dot);
            }

            if (dot > mmax) {
                float corr = __expf(mmax - dot);
                l *= corr;
#pragma unroll
                for (int d = 0; d < HD; d++) acc[d] *= corr;
                mmax = dot;
            }
            float p = __expf(dot - mmax);
            l += p;
#pragma unroll
            for (int d4 = 0; d4 < HD / 4; d4++) {
                float4 vv = *(const float4*)&Vs[j][d4 * 4];
                acc[d4 * 4 + 0] = fmaf(p, vv.x, acc[d4 * 4 + 0]);
                acc[d4 * 4 + 1] = fmaf(p, vv.y, acc[d4 * 4 + 1]);
                acc[d4 * 4 + 2] = fmaf(p, vv.z, acc[d4 * 4 + 2]);
                acc[d4 * 4 + 3] = fmaf(p, vv.w, acc[d4 * 4 + 3]);
            }
        }
    }

    const float inv = 1.f / l;
    float* orow = O + ((size_t)(b * SEQ + s)) * DIM + h * HD;
#pragma unroll
    for (int i = 0; i < HD / 4; i++) {
        float4 t;
        t.x = acc[i * 4 + 0] * inv;
        t.y = acc[i * 4 + 1] * inv;
        t.z = acc[i * 4 + 2] * inv;
        t.w = acc[i * 4 + 3] * inv;
        *(float4*)(orow + i * 4) = t;
    }
}

// ---------------------------------------------------------------------------
// Launch
// ---------------------------------------------------------------------------
extern "C" void kernel_launch(void* const* d_in, const int* in_sizes, int n_in,
                              void* d_out, int out_size)
{
    const float* x  = (const float*)d_in[0];
    const int* mask = (const int*)d_in[1];
    const float* Wq = (const float*)d_in[2];
    const float* bq = (const float*)d_in[3];
    const float* Wk = (const float*)d_in[4];
    const float* bk = (const float*)d_in[5];
    const float* Wv = (const float*)d_in[6];
    const float* bv = (const float*)d_in[7];
    const float* Wo = (const float*)d_in[8];
    const float* bo = (const float*)d_in[9];
    float* out = (float*)d_out;

    float *pQ, *pK, *pV, *pO;
    __nv_bfloat16 *pxh, *pxl, *pwh, *pwl, *poh, *pol;
    cudaGetSymbolAddress((void**)&pQ, g_Q);
    cudaGetSymbolAddress((void**)&pK, g_K);
    cudaGetSymbolAddress((void**)&pV, g_V);
    cudaGetSymbolAddress((void**)&pO, g_O);
    cudaGetSymbolAddress((void**)&pxh, g_xh);
    cudaGetSymbolAddress((void**)&pxl, g_xl);
    cudaGetSymbolAddress((void**)&pwh, g_wh);
    cudaGetSymbolAddress((void**)&pwl, g_wl);
    cudaGetSymbolAddress((void**)&poh, g_oh);
    cudaGetSymbolAddress((void**)&pol, g_ol);

    cudaFuncSetAttribute(gemm_mma, cudaFuncAttributeMaxDynamicSharedMemorySize, GEMM_SMEM);

    const int NW = DIM * DIM;

    split_kernel<<<1024, 256>>>(x,  pxh, pxl, NROWS * DIM / 4);
    split_kernel<<<512, 256>>>(Wq, pwh + 0 * NW, pwl + 0 * NW, NW / 4);
    split_kernel<<<512, 256>>>(Wk, pwh + 1 * NW, pwl + 1 * NW, NW / 4);
    split_kernel<<<512, 256>>>(Wv, pwh + 2 * NW, pwl + 2 * NW, NW / 4);
    split_kernel<<<512, 256>>>(Wo, pwh + 3 * NW, pwl + 3 * NW, NW / 4);

    dim3 ggrid(DIM / BN, NROWS / BM);  // (8, 64)
    gemm_mma<<<ggrid, 256, GEMM_SMEM>>>(pxh, pxl, pwh + 0 * NW, pwl + 0 * NW, bq, pQ, 0, QK_SCALE);
    gemm_mma<<<ggrid, 256, GEMM_SMEM>>>(pxh, pxl, pwh + 1 * NW, pwl + 1 * NW, bk, pK, 0, 1.0f);
    gemm_mma<<<ggrid, 256, GEMM_SMEM>>>(pxh, pxl, pwh + 2 * NW, pwl + 2 * NW, bv, pV, 0, 1.0f);

    dim3 agrid(SEQ / ATTN_ROWS, BATCH * HEADS);
    attn_kernel<<<agrid, ATTN_ROWS>>>(pQ, pK, pV, mask, pO);

    split_kernel<<<1024, 256>>>(pO, poh, pol, NROWS * DIM / 4);
    gemm_mma<<<ggrid, 256, GEMM_SMEM>>>(poh, pol, pwh + 3 * NW, pwl + 3 * NW, bo, out, 1, 1.0f);
}

// round 5
// speedup vs baseline: 2.8766x; 2.0604x over previous
#include <cuda_runtime.h>
#include <cuda_bf16.h>
#include <math_constants.h>
#include <cstdint>

// Problem constants
#define BATCH 4
#define SEQ   2048
#define DIM   1024
#define HEADS 16
#define HD    64
#define NROWS (BATCH * SEQ)   // 8192
#define QK_SCALE 0.125f

__device__ __forceinline__ uint32_t smem_u32(const void* p) {
    uint32_t a;
    asm("{ .reg .u64 t; cvta.to.shared.u64 t, %1; cvt.u32.u64 %0, t; }" : "=r"(a) : "l"(p));
    return a;
}

__device__ __forceinline__ void mma16816(float* d, const uint32_t* a, const uint32_t* b) {
    asm volatile("mma.sync.aligned.m16n8k16.row.col.f32.bf16.bf16.f32 "
        "{%0,%1,%2,%3}, {%4,%5,%6,%7}, {%8,%9}, {%0,%1,%2,%3};"
        : "+f"(d[0]), "+f"(d[1]), "+f"(d[2]), "+f"(d[3])
        : "r"(a[0]), "r"(a[1]), "r"(a[2]), "r"(a[3]), "r"(b[0]), "r"(b[1]));
}
__device__ __forceinline__ void ldsm_x4(uint32_t* r, uint32_t addr) {
    asm volatile("ldmatrix.sync.aligned.m8n8.x4.shared.b16 {%0,%1,%2,%3}, [%4];"
        : "=r"(r[0]), "=r"(r[1]), "=r"(r[2]), "=r"(r[3]) : "r"(addr));
}
__device__ __forceinline__ void ldsm_x4t(uint32_t* r, uint32_t addr) {
    asm volatile("ldmatrix.sync.aligned.m8n8.x4.trans.shared.b16 {%0,%1,%2,%3}, [%4];"
        : "=r"(r[0]), "=r"(r[1]), "=r"(r[2]), "=r"(r[3]) : "r"(addr));
}
__device__ __forceinline__ void cpa16(uint32_t s, const void* g) {
    asm volatile("cp.async.cg.shared.global [%0], [%1], 16;" :: "r"(s), "l"(g));
}
// split v0,v1 into packed bf16 hi pair and lo pair
__device__ __forceinline__ void split_pack(float v0, float v1, uint32_t& hp, uint32_t& lp) {
    __nv_bfloat16 h0 = __float2bfloat16(v0), h1 = __float2bfloat16(v1);
    __nv_bfloat162 hh; hh.x = h0; hh.y = h1;
    hp = *reinterpret_cast<uint32_t*>(&hh);
    __nv_bfloat162 ll = __floats2bfloat162_rn(v0 - __bfloat162float(h0),
                                              v1 - __bfloat162float(h1));
    lp = *reinterpret_cast<uint32_t*>(&ll);
}

// ---------------------------------------------------------------------------
// Scratch (device globals)
// ---------------------------------------------------------------------------
#define QKV_ELEMS (BATCH * HEADS * SEQ * HD)
__device__ __nv_bfloat16 g_qh[QKV_ELEMS];
__device__ __nv_bfloat16 g_ql[QKV_ELEMS];
__device__ __nv_bfloat16 g_kh[QKV_ELEMS];
__device__ __nv_bfloat16 g_kl[QKV_ELEMS];
__device__ __nv_bfloat16 g_vh[QKV_ELEMS];
__device__ __nv_bfloat16 g_vl[QKV_ELEMS];
__device__ __nv_bfloat16 g_xh[NROWS * DIM];
__device__ __nv_bfloat16 g_xl[NROWS * DIM];
__device__ __nv_bfloat16 g_wh[4 * DIM * DIM];
__device__ __nv_bfloat16 g_wl[4 * DIM * DIM];
__device__ __nv_bfloat16 g_oh[NROWS * DIM];
__device__ __nv_bfloat16 g_ol[NROWS * DIM];

// ---------------------------------------------------------------------------
// fp32 -> (bf16 hi, bf16 lo) split
// ---------------------------------------------------------------------------
struct bf4 { __nv_bfloat16 v[4]; };

__global__ void split_kernel(const float* __restrict__ src,
                             __nv_bfloat16* __restrict__ hi,
                             __nv_bfloat16* __restrict__ lo, int n4)
{
    for (int i = blockIdx.x * blockDim.x + threadIdx.x; i < n4; i += gridDim.x * blockDim.x) {
        float4 x = ((const float4*)src)[i];
        bf4 h, l;
        float f[4] = {x.x, x.y, x.z, x.w};
#pragma unroll
        for (int j = 0; j < 4; j++) {
            __nv_bfloat16 hv = __float2bfloat16(f[j]);
            h.v[j] = hv;
            l.v[j] = __float2bfloat16(f[j] - __bfloat162float(hv));
        }
        ((bf4*)hi)[i] = h;
        ((bf4*)lo)[i] = l;
    }
}

// ---------------------------------------------------------------------------
// bf16x3 GEMM via mma.sync.m16n8k16 (fp32 accum)
// mode 0: write bf16 hi/lo to [B,H,S,Hd] (scaled); mode 1: fp32 row-major
// ---------------------------------------------------------------------------
#define BM 128
#define BN 128
#define BK 32
#define NKC (DIM / BK)
#define ROWPAD 40
#define TILE_SB (128 * ROWPAD * 2)
#define STAGE_SB (4 * TILE_SB)
#define GEMM_SMEM (2 * STAGE_SB)

__global__ __launch_bounds__(256, 1)
void gemm_mma(const __nv_bfloat16* __restrict__ Ahi, const __nv_bfloat16* __restrict__ Alo,
              const __nv_bfloat16* __restrict__ Whi, const __nv_bfloat16* __restrict__ Wlo,
              const float* __restrict__ bias, float* __restrict__ C,
              __nv_bfloat16* __restrict__ Chi, __nv_bfloat16* __restrict__ Clo,
              int mode, float scale)
{
    extern __shared__ char smraw[];
    const uint32_t smem_base = smem_u32(smraw);

    const int tid = threadIdx.x;
    const int lane = tid & 31;
    const int wid = tid >> 5;
    const int wm = wid & 1;
    const int wn = wid >> 1;
    const int row0 = blockIdx.y * BM;
    const int col0 = blockIdx.x * BN;

    const uint4* srcs[4] = {(const uint4*)Ahi, (const uint4*)Alo,
                            (const uint4*)Whi, (const uint4*)Wlo};
    const int bases[4] = {row0, row0, col0, col0};

    float acc[4][4][4];
#pragma unroll
    for (int i = 0; i < 4; i++)
#pragma unroll
        for (int j = 0; j < 4; j++)
#pragma unroll
            for (int r = 0; r < 4; r++) acc[i][j][r] = 0.f;

    const int r0l = tid >> 2;
    const int cu  = tid & 3;

#define ISSUE_STAGE(kc, buf) do { \
    uint32_t sb_ = smem_base + (buf) * STAGE_SB; \
    _Pragma("unroll") \
    for (int t_ = 0; t_ < 4; t_++) { \
        _Pragma("unroll") \
        for (int j_ = 0; j_ < 2; j_++) { \
            int r_ = r0l + j_ * 64; \
            const uint4* g_ = srcs[t_] + (size_t)(bases[t_] + r_) * 128 + (kc) * 4 + cu; \
            uint32_t s_ = sb_ + t_ * TILE_SB + r_ * 80 + cu * 16; \
            asm volatile("cp.async.cg.shared.global [%0], [%1], 16;" :: "r"(s_), "l"(g_)); \
        } \
    } \
    asm volatile("cp.async.commit_group;" ::: "memory"); \
} while (0)

    ISSUE_STAGE(0, 0);

    for (int kc = 0; kc < NKC; kc++) {
        const int buf = kc & 1;
        if (kc + 1 < NKC) {
            ISSUE_STAGE(kc + 1, buf ^ 1);
            asm volatile("cp.async.wait_group 1;" ::: "memory");
        } else {
            asm volatile("cp.async.wait_group 0;" ::: "memory");
        }
        __syncthreads();

        const uint32_t sb = smem_base + buf * STAGE_SB;
#pragma unroll
        for (int s = 0; s < 2; s++) {
            uint32_t a_h[4][4], a_l[4][4];
            const uint32_t acol = s * 32 + ((lane >> 4) << 4);
#pragma unroll
            for (int mt = 0; mt < 4; mt++) {
                const int r = wm * 64 + mt * 16 + (lane & 15);
                uint32_t addr = sb + r * 80 + acol;
                ldsm_x4(a_h[mt], addr);
                ldsm_x4(a_l[mt], addr + TILE_SB);
            }
            uint32_t b_h[4][2], b_l[4][2];
            const int mat = lane >> 3;
            const int mr = lane & 7;
            const uint32_t bcol = s * 32 + ((mat & 1) << 4);
#pragma unroll
            for (int np = 0; np < 2; np++) {
                const int n = wn * 32 + (np * 2 + (mat >> 1)) * 8 + mr;
                uint32_t addr = sb + 2 * TILE_SB + n * 80 + bcol;
                uint32_t q[4];
                ldsm_x4(q, addr);
                b_h[np * 2][0] = q[0]; b_h[np * 2][1] = q[1];
                b_h[np * 2 + 1][0] = q[2]; b_h[np * 2 + 1][1] = q[3];
                ldsm_x4(q, addr + TILE_SB);
                b_l[np * 2][0] = q[0]; b_l[np * 2][1] = q[1];
                b_l[np * 2 + 1][0] = q[2]; b_l[np * 2 + 1][1] = q[3];
            }
#pragma unroll
            for (int mt = 0; mt < 4; mt++)
#pragma unroll
                for (int nt = 0; nt < 4; nt++) {
                    mma16816(acc[mt][nt], a_h[mt], b_h[nt]);
                    mma16816(acc[mt][nt], a_h[mt], b_l[nt]);
                    mma16816(acc[mt][nt], a_l[mt], b_h[nt]);
                }
        }
        __syncthreads();
    }

    const int g = lane >> 2;
    const int tg2 = (lane & 3) * 2;
#pragma unroll
    for (int mt = 0; mt < 4; mt++) {
        const int rb = row0 + wm * 64 + mt * 16 + g;
#pragma unroll
        for (int nt = 0; nt < 4; nt++) {
            const int m = col0 + wn * 32 + nt * 8 + tg2;
            const float b0 = bias[m], b1 = bias[m + 1];
#pragma unroll
            for (int hh = 0; hh < 2; hh++) {
                const int n = rb + hh * 8;
                float v0 = acc[mt][nt][hh * 2 + 0] + b0;
                float v1 = acc[mt][nt][hh * 2 + 1] + b1;
                if (mode == 0) {
                    v0 *= scale; v1 *= scale;
                    const int b = n >> 11;
                    const int sq = n & (SEQ - 1);
                    const int h = m >> 6;
                    const int hd = m & (HD - 1);
                    uint32_t hp, lp;
                    split_pack(v0, v1, hp, lp);
                    const size_t o = (((size_t)(b * HEADS + h) * SEQ) + sq) * HD + hd;
                    *(uint32_t*)&Chi[o] = hp;
                    *(uint32_t*)&Clo[o] = lp;
                } else {
                    float2 w; w.x = v0; w.y = v1;
                    *(float2*)&C[(size_t)n * DIM + m] = w;
                }
            }
        }
    }
}

// ---------------------------------------------------------------------------
// MMA flash attention (bf16x3, fp32 softmax)
// CTA: 256 threads (8 warps), 128 q-rows of one (b,h). 64-key tiles.
// ---------------------------------------------------------------------------
#define AQ 128
#define AK 64
#define APAD 72                       // padded row (bf16): 144 B
#define NT_K (SEQ / AK)               // 32
#define SM_QH 0
#define SM_QL 18432
#define SM_ST0 36864
#define ST_STRIDE 37120
#define OFF_KH 0
#define OFF_KL 9216
#define OFF_VH 18432
#define OFF_VL 27648
#define OFF_MSK 36864
#define ATTN_SMEM (SM_ST0 + 2 * ST_STRIDE)   // 111104

__global__ __launch_bounds__(256, 1)
void attn_mma(const __nv_bfloat16* __restrict__ Qh_, const __nv_bfloat16* __restrict__ Ql_,
              const __nv_bfloat16* __restrict__ Kh_, const __nv_bfloat16* __restrict__ Kl_,
              const __nv_bfloat16* __restrict__ Vh_, const __nv_bfloat16* __restrict__ Vl_,
              const int* __restrict__ mask,
              __nv_bfloat16* __restrict__ Oh_, __nv_bfloat16* __restrict__ Ol_)
{
    extern __shared__ char sm[];
    const uint32_t sb = smem_u32(sm);
    const int tid = threadIdx.x, lane = tid & 31, wid = tid >> 5;
    const int bh = blockIdx.y, b = bh >> 4, h = bh & 15;
    const int q0 = blockIdx.x * AQ;
    const size_t base = (size_t)bh * SEQ * HD;
    const int* mrow = mask + b * SEQ;

#define ISSUE_KV(tile, stage) do { \
    uint32_t st_ = sb + SM_ST0 + (stage) * ST_STRIDE; \
    _Pragma("unroll") \
    for (int i_ = 0; i_ < 2; i_++) { \
        int idx_ = tid + i_ * 256, r_ = idx_ >> 3, c_ = idx_ & 7; \
        size_t go_ = base + (size_t)((tile) * AK + r_) * HD + c_ * 8; \
        uint32_t so_ = r_ * 144 + c_ * 16; \
        cpa16(st_ + OFF_KH + so_, Kh_ + go_); \
        cpa16(st_ + OFF_KL + so_, Kl_ + go_); \
        cpa16(st_ + OFF_VH + so_, Vh_ + go_); \
        cpa16(st_ + OFF_VL + so_, Vl_ + go_); \
    } \
    if (tid < 16) cpa16(st_ + OFF_MSK + tid * 16, mrow + (tile) * AK + tid * 4); \
    asm volatile("cp.async.commit_group;" ::: "memory"); \
} while (0)

    // G0: Q + KV tile 0;  G1: KV tile 1
    {
#pragma unroll
        for (int i = 0; i < 4; i++) {
            int idx = tid + i * 256, r = idx >> 3, c = idx & 7;
            size_t go = base + (size_t)(q0 + r) * HD + c * 8;
            cpa16(sb + SM_QH + r * 144 + c * 16, Qh_ + go);
            cpa16(sb + SM_QL + r * 144 + c * 16, Ql_ + go);
        }
        ISSUE_KV(0, 0);   // commits G0 (Q included)
    }
    ISSUE_KV(1, 1);       // G1

    asm volatile("cp.async.wait_group 1;" ::: "memory");
    __syncthreads();

    // Q fragments (held in registers for whole kernel)
    uint32_t qh[4][4], ql[4][4];
    {
        const int qrow = wid * 16 + (lane & 15);
        const int qc = (lane >> 4) * 8;
#pragma unroll
        for (int kf = 0; kf < 4; kf++) {
            uint32_t a = sb + SM_QH + qrow * 144 + (kf * 16 + qc) * 2;
            ldsm_x4(qh[kf], a);
            ldsm_x4(ql[kf], a + (SM_QL - SM_QH));
        }
    }

    float O[8][4];
#pragma unroll
    for (int i = 0; i < 8; i++)
#pragma unroll
        for (int j = 0; j < 4; j++) O[i][j] = 0.f;
    float mrun0 = -1e30f, mrun1 = -1e30f, lrun0 = 0.f, lrun1 = 0.f;

    const int kc2 = (lane & 3) * 2;
    const int krow = ((lane >> 4) & 1) * 8 + (lane & 7);
    const int kcol = ((lane >> 3) & 1) * 8;
    const int vrow = ((lane >> 3) & 1) * 8 + (lane & 7);
    const int vcol = ((lane >> 4) & 1) * 8;

    for (int t = 0; t < NT_K; t++) {
        const int stg = t & 1;
        if (t < NT_K - 1) asm volatile("cp.async.wait_group 1;" ::: "memory");
        else              asm volatile("cp.async.wait_group 0;" ::: "memory");
        __syncthreads();
        const uint32_t st = sb + SM_ST0 + stg * ST_STRIDE;
        const char* stc = sm + SM_ST0 + stg * ST_STRIDE;

        // ---- S = Qh*Kh + Qh*Kl + Ql*Kh ----
        float S[8][4];
#pragma unroll
        for (int i = 0; i < 8; i++)
#pragma unroll
            for (int j = 0; j < 4; j++) S[i][j] = 0.f;

#pragma unroll
        for (int kf = 0; kf < 4; kf++) {
            uint32_t kb[4][4], klr[4][4];
#pragma unroll
            for (int np = 0; np < 4; np++) {
                uint32_t a = st + OFF_KH + (np * 16 + krow) * 144 + (kf * 16 + kcol) * 2;
                ldsm_x4(kb[np], a);
                ldsm_x4(klr[np], a + (OFF_KL - OFF_KH));
            }
#pragma unroll
            for (int np = 0; np < 4; np++) {
                mma16816(S[2 * np],     qh[kf], &kb[np][0]);
                mma16816(S[2 * np],     qh[kf], &klr[np][0]);
                mma16816(S[2 * np],     ql[kf], &kb[np][0]);
                mma16816(S[2 * np + 1], qh[kf], &kb[np][2]);
                mma16816(S[2 * np + 1], qh[kf], &klr[np][2]);
                mma16816(S[2 * np + 1], ql[kf], &kb[np][2]);
            }
        }

        // ---- mask + online softmax ----
        float tmax0 = -1e30f, tmax1 = -1e30f;
#pragma unroll
        for (int nt = 0; nt < 8; nt++) {
            const int k = nt * 8 + kc2;
            const int m0 = *(const int*)(stc + OFF_MSK + k * 4);
            const int m1 = *(const int*)(stc + OFF_MSK + k * 4 + 4);
            if (m0) { S[nt][0] = -CUDART_INF_F; S[nt][2] = -CUDART_INF_F; }
            if (m1) { S[nt][1] = -CUDART_INF_F; S[nt][3] = -CUDART_INF_F; }
            tmax0 = fmaxf(tmax0, fmaxf(S[nt][0], S[nt][1]));
            tmax1 = fmaxf(tmax1, fmaxf(S[nt][2], S[nt][3]));
        }
        tmax0 = fmaxf(tmax0, __shfl_xor_sync(0xFFFFFFFF, tmax0, 1));
        tmax0 = fmaxf(tmax0, __shfl_xor_sync(0xFFFFFFFF, tmax0, 2));
        tmax1 = fmaxf(tmax1, __shfl_xor_sync(0xFFFFFFFF, tmax1, 1));
        tmax1 = fmaxf(tmax1, __shfl_xor_sync(0xFFFFFFFF, tmax1, 2));

        const float mn0 = fmaxf(mrun0, tmax0);
        const float mn1 = fmaxf(mrun1, tmax1);
        const float sc0 = __expf(mrun0 - mn0);
        const float sc1 = __expf(mrun1 - mn1);
        mrun0 = mn0; mrun1 = mn1;

        float ts0 = 0.f, ts1 = 0.f;
        uint32_t ph[8][2], pl[8][2];
#pragma unroll
        for (int nt = 0; nt < 8; nt++) {
            const float p0 = __expf(S[nt][0] - mn0);
            const float p1 = __expf(S[nt][1] - mn0);
            const float p2 = __expf(S[nt][2] - mn1);
            const float p3 = __expf(S[nt][3] - mn1);
            ts0 += p0 + p1; ts1 += p2 + p3;
            split_pack(p0, p1, ph[nt][0], pl[nt][0]);
            split_pack(p2, p3, ph[nt][1], pl[nt][1]);
        }
        ts0 += __shfl_xor_sync(0xFFFFFFFF, ts0, 1);
        ts0 += __shfl_xor_sync(0xFFFFFFFF, ts0, 2);
        ts1 += __shfl_xor_sync(0xFFFFFFFF, ts1, 1);
        ts1 += __shfl_xor_sync(0xFFFFFFFF, ts1, 2);
        lrun0 = lrun0 * sc0 + ts0;
        lrun1 = lrun1 * sc1 + ts1;
#pragma unroll
        for (int nt = 0; nt < 8; nt++) {
            O[nt][0] *= sc0; O[nt][1] *= sc0;
            O[nt][2] *= sc1; O[nt][3] *= sc1;
        }

        // ---- O += Ph*Vh + Ph*Vl + Pl*Vh ----
#pragma unroll
        for (int kf = 0; kf < 4; kf++) {
            uint32_t ah[4] = {ph[2 * kf][0], ph[2 * kf][1], ph[2 * kf + 1][0], ph[2 * kf + 1][1]};
            uint32_t al[4] = {pl[2 * kf][0], pl[2 * kf][1], pl[2 * kf + 1][0], pl[2 * kf + 1][1]};
            uint32_t vb[4][4], vlr[4][4];
#pragma unroll
            for (int np = 0; np < 4; np++) {
                uint32_t a = st + OFF_VH + (kf * 16 + vrow) * 144 + (np * 16 + vcol) * 2;
                ldsm_x4t(vb[np], a);
                ldsm_x4t(vlr[np], a + (OFF_VL - OFF_VH));
            }
#pragma unroll
            for (int np = 0; np < 4; np++) {
                mma16816(O[2 * np],     ah, &vb[np][0]);
                mma16816(O[2 * np],     ah, &vlr[np][0]);
                mma16816(O[2 * np],     al, &vb[np][0]);
                mma16816(O[2 * np + 1], ah, &vb[np][2]);
                mma16816(O[2 * np + 1], ah, &vlr[np][2]);
                mma16816(O[2 * np + 1], al, &vb[np][2]);
            }
        }

        __syncthreads();
        if (t + 2 < NT_K) ISSUE_KV(t + 2, stg);
    }

    // ---- epilogue: O/l -> bf16 hi/lo at [b*SEQ+s][h*64+col] ----
    const float inv0 = 1.f / lrun0;
    const float inv1 = 1.f / lrun1;
    const int g = lane >> 2;
    const size_t row0 = (size_t)(b * SEQ + q0 + wid * 16 + g) * DIM + h * HD;
    const size_t row1 = row0 + (size_t)8 * DIM;
#pragma unroll
    for (int nt = 0; nt < 8; nt++) {
        const int col = nt * 8 + kc2;
        uint32_t hp, lp;
        split_pack(O[nt][0] * inv0, O[nt][1] * inv0, hp, lp);
        *(uint32_t*)&Oh_[row0 + col] = hp;
        *(uint32_t*)&Ol_[row0 + col] = lp;
        split_pack(O[nt][2] * inv1, O[nt][3] * inv1, hp, lp);
        *(uint32_t*)&Oh_[row1 + col] = hp;
        *(uint32_t*)&Ol_[row1 + col] = lp;
    }
}

// ---------------------------------------------------------------------------
// Launch
// ---------------------------------------------------------------------------
extern "C" void kernel_launch(void* const* d_in, const int* in_sizes, int n_in,
                              void* d_out, int out_size)
{
    const float* x  = (const float*)d_in[0];
    const int* mask = (const int*)d_in[1];
    const float* Wq = (const float*)d_in[2];
    const float* bq = (const float*)d_in[3];
    const float* Wk = (const float*)d_in[4];
    const float* bk = (const float*)d_in[5];
    const float* Wv = (const float*)d_in[6];
    const float* bv = (const float*)d_in[7];
    const float* Wo = (const float*)d_in[8];
    const float* bo = (const float*)d_in[9];
    float* out = (float*)d_out;

    __nv_bfloat16 *pqh, *pql, *pkh, *pkl, *pvh, *pvl;
    __nv_bfloat16 *pxh, *pxl, *pwh, *pwl, *poh, *pol;
    cudaGetSymbolAddress((void**)&pqh, g_qh);
    cudaGetSymbolAddress((void**)&pql, g_ql);
    cudaGetSymbolAddress((void**)&pkh, g_kh);
    cudaGetSymbolAddress((void**)&pkl, g_kl);
    cudaGetSymbolAddress((void**)&pvh, g_vh);
    cudaGetSymbolAddress((void**)&pvl, g_vl);
    cudaGetSymbolAddress((void**)&pxh, g_xh);
    cudaGetSymbolAddress((void**)&pxl, g_xl);
    cudaGetSymbolAddress((void**)&pwh, g_wh);
    cudaGetSymbolAddress((void**)&pwl, g_wl);
    cudaGetSymbolAddress((void**)&poh, g_oh);
    cudaGetSymbolAddress((void**)&pol, g_ol);

    cudaFuncSetAttribute(gemm_mma, cudaFuncAttributeMaxDynamicSharedMemorySize, GEMM_SMEM);
    cudaFuncSetAttribute(attn_mma, cudaFuncAttributeMaxDynamicSharedMemorySize, ATTN_SMEM);

    const int NW = DIM * DIM;

    split_kernel<<<1024, 256>>>(x,  pxh, pxl, NROWS * DIM / 4);
    split_kernel<<<512, 256>>>(Wq, pwh + 0 * NW, pwl + 0 * NW, NW / 4);
    split_kernel<<<512, 256>>>(Wk, pwh + 1 * NW, pwl + 1 * NW, NW / 4);
    split_kernel<<<512, 256>>>(Wv, pwh + 2 * NW, pwl + 2 * NW, NW / 4);
    split_kernel<<<512, 256>>>(Wo, pwh + 3 * NW, pwl + 3 * NW, NW / 4);

    dim3 ggrid(DIM / BN, NROWS / BM);  // (8, 64)
    gemm_mma<<<ggrid, 256, GEMM_SMEM>>>(pxh, pxl, pwh + 0 * NW, pwl + 0 * NW, bq,
                                        nullptr, pqh, pql, 0, QK_SCALE);
    gemm_mma<<<ggrid, 256, GEMM_SMEM>>>(pxh, pxl, pwh + 1 * NW, pwl + 1 * NW, bk,
                                        nullptr, pkh, pkl, 0, 1.0f);
    gemm_mma<<<ggrid, 256, GEMM_SMEM>>>(pxh, pxl, pwh + 2 * NW, pwl + 2 * NW, bv,
                                        nullptr, pvh, pvl, 0, 1.0f);

    dim3 agrid(SEQ / AQ, BATCH * HEADS);  // (16, 64)
    attn_mma<<<agrid, 256, ATTN_SMEM>>>(pqh, pql, pkh, pkl, pvh, pvl, mask, poh, pol);

    gemm_mma<<<ggrid, 256, GEMM_SMEM>>>(poh, pol, pwh + 3 * NW, pwl + 3 * NW, bo,
                                        out, nullptr, nullptr, 1, 1.0f);
}

// round 6
// speedup vs baseline: 2.9667x; 1.0313x over previous
#include <cuda_runtime.h>
#include <cuda_bf16.h>
#include <math_constants.h>
#include <cstdint>

// Problem constants
#define BATCH 4
#define SEQ   2048
#define DIM   1024
#define HEADS 16
#define HD    64
#define NROWS (BATCH * SEQ)   // 8192
#define QK_SCALE 0.125f

__device__ __forceinline__ uint32_t smem_u32(const void* p) {
    uint32_t a;
    asm("{ .reg .u64 t; cvta.to.shared.u64 t, %1; cvt.u32.u64 %0, t; }" : "=r"(a) : "l"(p));
    return a;
}
__device__ __forceinline__ void mma16816(float* d, const uint32_t* a, const uint32_t* b) {
    asm volatile("mma.sync.aligned.m16n8k16.row.col.f32.bf16.bf16.f32 "
        "{%0,%1,%2,%3}, {%4,%5,%6,%7}, {%8,%9}, {%0,%1,%2,%3};"
        : "+f"(d[0]), "+f"(d[1]), "+f"(d[2]), "+f"(d[3])
        : "r"(a[0]), "r"(a[1]), "r"(a[2]), "r"(a[3]), "r"(b[0]), "r"(b[1]));
}
__device__ __forceinline__ void ldsm_x4(uint32_t* r, uint32_t addr) {
    asm volatile("ldmatrix.sync.aligned.m8n8.x4.shared.b16 {%0,%1,%2,%3}, [%4];"
        : "=r"(r[0]), "=r"(r[1]), "=r"(r[2]), "=r"(r[3]) : "r"(addr));
}
__device__ __forceinline__ void ldsm_x4t(uint32_t* r, uint32_t addr) {
    asm volatile("ldmatrix.sync.aligned.m8n8.x4.trans.shared.b16 {%0,%1,%2,%3}, [%4];"
        : "=r"(r[0]), "=r"(r[1]), "=r"(r[2]), "=r"(r[3]) : "r"(addr));
}
__device__ __forceinline__ void cpa16(uint32_t s, const void* g) {
    asm volatile("cp.async.cg.shared.global [%0], [%1], 16;" :: "r"(s), "l"(g));
}
__device__ __forceinline__ void split_pack(float v0, float v1, uint32_t& hp, uint32_t& lp) {
    __nv_bfloat16 h0 = __float2bfloat16(v0), h1 = __float2bfloat16(v1);
    __nv_bfloat162 hh; hh.x = h0; hh.y = h1;
    hp = *reinterpret_cast<uint32_t*>(&hh);
    __nv_bfloat162 ll = __floats2bfloat162_rn(v0 - __bfloat162float(h0),
                                              v1 - __bfloat162float(h1));
    lp = *reinterpret_cast<uint32_t*>(&ll);
}

// ---------------------------------------------------------------------------
// Scratch
// ---------------------------------------------------------------------------
#define QKV_ELEMS (BATCH * HEADS * SEQ * HD)
__device__ __nv_bfloat16 g_qh[QKV_ELEMS];
__device__ __nv_bfloat16 g_ql[QKV_ELEMS];
__device__ __nv_bfloat16 g_kh[QKV_ELEMS];
__device__ __nv_bfloat16 g_kl[QKV_ELEMS];
__device__ __nv_bfloat16 g_vh[QKV_ELEMS];
__device__ __nv_bfloat16 g_vl[QKV_ELEMS];
__device__ __nv_bfloat16 g_xh[NROWS * DIM];
__device__ __nv_bfloat16 g_xl[NROWS * DIM];
__device__ __nv_bfloat16 g_wh[4 * DIM * DIM];
__device__ __nv_bfloat16 g_wl[4 * DIM * DIM];
__device__ __nv_bfloat16 g_oh[NROWS * DIM];
__device__ __nv_bfloat16 g_ol[NROWS * DIM];

// ---------------------------------------------------------------------------
// fp32 -> bf16 hi/lo split
// ---------------------------------------------------------------------------
struct bf4 { __nv_bfloat16 v[4]; };

__global__ void split_kernel(const float* __restrict__ src,
                             __nv_bfloat16* __restrict__ hi,
                             __nv_bfloat16* __restrict__ lo, int n4)
{
    for (int i = blockIdx.x * blockDim.x + threadIdx.x; i < n4; i += gridDim.x * blockDim.x) {
        float4 x = ((const float4*)src)[i];
        bf4 h, l;
        float f[4] = {x.x, x.y, x.z, x.w};
#pragma unroll
        for (int j = 0; j < 4; j++) {
            __nv_bfloat16 hv = __float2bfloat16(f[j]);
            h.v[j] = hv;
            l.v[j] = __float2bfloat16(f[j] - __bfloat162float(hv));
        }
        ((bf4*)hi)[i] = h;
        ((bf4*)lo)[i] = l;
    }
}

// ---------------------------------------------------------------------------
// bf16x3 GEMM, 4-stage cp.async pipeline, single sync per k-iter
// ---------------------------------------------------------------------------
#define BM 128
#define BN 128
#define BK 32
#define NKC (DIM / BK)
#define TILE_SB (128 * 80)          // 10240 B per operand tile (row pad 80 B)
#define STAGE_SB (4 * TILE_SB)      // 40960 B
#define NSTG 4
#define GEMM_SMEM (NSTG * STAGE_SB) // 163840 B

// Core of the GEMM. qkv mode: writes bf16 hi/lo scattered; else fp32 row-major.
__device__ __forceinline__ void gemm_body(
    const __nv_bfloat16* Ahi, const __nv_bfloat16* Alo,
    const __nv_bfloat16* Whi, const __nv_bfloat16* Wlo,
    const float* bias, float* C,
    __nv_bfloat16* Chi, __nv_bfloat16* Clo,
    int mode, float scale, int row0, int col0)
{
    extern __shared__ char smraw[];
    const uint32_t smem_base = smem_u32(smraw);

    const int tid = threadIdx.x;
    const int lane = tid & 31;
    const int wid = tid >> 5;
    const int wm = wid & 1;
    const int wn = wid >> 1;

    const uint4* srcs[4] = {(const uint4*)Ahi, (const uint4*)Alo,
                            (const uint4*)Whi, (const uint4*)Wlo};
    const int bases[4] = {row0, row0, col0, col0};

    float acc[4][4][4];
#pragma unroll
    for (int i = 0; i < 4; i++)
#pragma unroll
        for (int j = 0; j < 4; j++)
#pragma unroll
            for (int r = 0; r < 4; r++) acc[i][j][r] = 0.f;

    const int r0l = tid >> 2;
    const int cu  = tid & 3;

#define G_ISSUE(kc, buf) do { \
    uint32_t sb_ = smem_base + (buf) * STAGE_SB; \
    _Pragma("unroll") \
    for (int t_ = 0; t_ < 4; t_++) { \
        _Pragma("unroll") \
        for (int j_ = 0; j_ < 2; j_++) { \
            int r_ = r0l + j_ * 64; \
            const uint4* g_ = srcs[t_] + (size_t)(bases[t_] + r_) * 128 + (kc) * 4 + cu; \
            uint32_t s_ = sb_ + t_ * TILE_SB + r_ * 80 + cu * 16; \
            cpa16(s_, g_); \
        } \
    } \
    asm volatile("cp.async.commit_group;" ::: "memory"); \
} while (0)

    G_ISSUE(0, 0);
    G_ISSUE(1, 1);
    G_ISSUE(2, 2);

    for (int kc = 0; kc < NKC; kc++) {
        const int buf = kc & 3;
        asm volatile("cp.async.wait_group 2;" ::: "memory");
        __syncthreads();
        if (kc + 3 < NKC) G_ISSUE(kc + 3, (kc + 3) & 3);

        const uint32_t sb = smem_base + buf * STAGE_SB;
#pragma unroll
        for (int s = 0; s < 2; s++) {
            uint32_t a_h[4][4], a_l[4][4];
            const uint32_t acol = s * 32 + ((lane >> 4) << 4);
#pragma unroll
            for (int mt = 0; mt < 4; mt++) {
                const int r = wm * 64 + mt * 16 + (lane & 15);
                uint32_t addr = sb + r * 80 + acol;
                ldsm_x4(a_h[mt], addr);
                ldsm_x4(a_l[mt], addr + TILE_SB);
            }
            uint32_t b_h[4][2], b_l[4][2];
            const int mat = lane >> 3;
            const int mr = lane & 7;
            const uint32_t bcol = s * 32 + ((mat & 1) << 4);
#pragma unroll
            for (int np = 0; np < 2; np++) {
                const int n = wn * 32 + (np * 2 + (mat >> 1)) * 8 + mr;
                uint32_t addr = sb + 2 * TILE_SB + n * 80 + bcol;
                uint32_t q[4];
                ldsm_x4(q, addr);
                b_h[np * 2][0] = q[0]; b_h[np * 2][1] = q[1];
                b_h[np * 2 + 1][0] = q[2]; b_h[np * 2 + 1][1] = q[3];
                ldsm_x4(q, addr + TILE_SB);
                b_l[np * 2][0] = q[0]; b_l[np * 2][1] = q[1];
                b_l[np * 2 + 1][0] = q[2]; b_l[np * 2 + 1][1] = q[3];
            }
#pragma unroll
            for (int mt = 0; mt < 4; mt++)
#pragma unroll
                for (int nt = 0; nt < 4; nt++) {
                    mma16816(acc[mt][nt], a_h[mt], b_h[nt]);
                    mma16816(acc[mt][nt], a_h[mt], b_l[nt]);
                    mma16816(acc[mt][nt], a_l[mt], b_h[nt]);
                }
        }
    }

    const int g = lane >> 2;
    const int tg2 = (lane & 3) * 2;
#pragma unroll
    for (int mt = 0; mt < 4; mt++) {
        const int rb = row0 + wm * 64 + mt * 16 + g;
#pragma unroll
        for (int nt = 0; nt < 4; nt++) {
            const int m = col0 + wn * 32 + nt * 8 + tg2;
            const float b0 = bias[m], b1 = bias[m + 1];
#pragma unroll
            for (int hh = 0; hh < 2; hh++) {
                const int n = rb + hh * 8;
                float v0 = acc[mt][nt][hh * 2 + 0] + b0;
                float v1 = acc[mt][nt][hh * 2 + 1] + b1;
                if (mode == 0) {
                    v0 *= scale; v1 *= scale;
                    const int b = n >> 11;
                    const int sq = n & (SEQ - 1);
                    const int h = m >> 6;
                    const int hd = m & (HD - 1);
                    uint32_t hp, lp;
                    split_pack(v0, v1, hp, lp);
                    const size_t o = (((size_t)(b * HEADS + h) * SEQ) + sq) * HD + hd;
                    *(uint32_t*)&Chi[o] = hp;
                    *(uint32_t*)&Clo[o] = lp;
                } else {
                    float2 w; w.x = v0; w.y = v1;
                    *(float2*)&C[(size_t)n * DIM + m] = w;
                }
            }
        }
    }
}

// Fused Q/K/V projection: grid (24, 64); blockIdx.x>>3 selects weight/output.
__global__ __launch_bounds__(256, 1)
void gemm_qkv(const __nv_bfloat16* __restrict__ xh, const __nv_bfloat16* __restrict__ xl,
              const __nv_bfloat16* __restrict__ wh, const __nv_bfloat16* __restrict__ wl,
              const float* __restrict__ bq, const float* __restrict__ bk,
              const float* __restrict__ bv,
              __nv_bfloat16* __restrict__ qh, __nv_bfloat16* __restrict__ ql,
              __nv_bfloat16* __restrict__ kh, __nv_bfloat16* __restrict__ kl,
              __nv_bfloat16* __restrict__ vh, __nv_bfloat16* __restrict__ vl)
{
    const int w = blockIdx.x >> 3;
    const int col0 = (blockIdx.x & 7) * BN;
    const int row0 = blockIdx.y * BM;
    const int NW = DIM * DIM;
    const float* bias = (w == 0) ? bq : (w == 1) ? bk : bv;
    __nv_bfloat16* Chi = (w == 0) ? qh : (w == 1) ? kh : vh;
    __nv_bfloat16* Clo = (w == 0) ? ql : (w == 1) ? kl : vl;
    const float scale = (w == 0) ? QK_SCALE : 1.0f;
    gemm_body(xh, xl, wh + (size_t)w * NW, wl + (size_t)w * NW, bias,
              nullptr, Chi, Clo, 0, scale, row0, col0);
}

// Output projection: fp32 row-major out.
__global__ __launch_bounds__(256, 1)
void gemm_out(const __nv_bfloat16* __restrict__ oh, const __nv_bfloat16* __restrict__ ol,
              const __nv_bfloat16* __restrict__ wh, const __nv_bfloat16* __restrict__ wl,
              const float* __restrict__ bias, float* __restrict__ out)
{
    gemm_body(oh, ol, wh, wl, bias, out, nullptr, nullptr, 1, 1.0f,
              blockIdx.y * BM, blockIdx.x * BN);
}

// ---------------------------------------------------------------------------
// MMA flash attention, 4-stage KV pipeline
// ---------------------------------------------------------------------------
#define AQ 128
#define AK 64
#define NT_K (SEQ / AK)
#define SM_QH 0
#define SM_QL 18432
#define SM_ST0 36864
#define ST_STRIDE 37120
#define OFF_KH 0
#define OFF_KL 9216
#define OFF_VH 18432
#define OFF_VL 27648
#define OFF_MSK 36864
#define A_NSTG 4
#define ATTN_SMEM (SM_ST0 + A_NSTG * ST_STRIDE)   // 185344

__global__ __launch_bounds__(256, 1)
void attn_mma(const __nv_bfloat16* __restrict__ Qh_, const __nv_bfloat16* __restrict__ Ql_,
              const __nv_bfloat16* __restrict__ Kh_, const __nv_bfloat16* __restrict__ Kl_,
              const __nv_bfloat16* __restrict__ Vh_, const __nv_bfloat16* __restrict__ Vl_,
              const int* __restrict__ mask,
              __nv_bfloat16* __restrict__ Oh_, __nv_bfloat16* __restrict__ Ol_)
{
    extern __shared__ char sm[];
    const uint32_t sb = smem_u32(sm);
    const int tid = threadIdx.x, lane = tid & 31, wid = tid >> 5;
    const int bh = blockIdx.y, b = bh >> 4, h = bh & 15;
    const int q0 = blockIdx.x * AQ;
    const size_t base = (size_t)bh * SEQ * HD;
    const int* mrow = mask + b * SEQ;

#define A_ISSUE(tile, stage) do { \
    uint32_t st_ = sb + SM_ST0 + (stage) * ST_STRIDE; \
    _Pragma("unroll") \
    for (int i_ = 0; i_ < 2; i_++) { \
        int idx_ = tid + i_ * 256, r_ = idx_ >> 3, c_ = idx_ & 7; \
        size_t go_ = base + (size_t)((tile) * AK + r_) * HD + c_ * 8; \
        uint32_t so_ = r_ * 144 + c_ * 16; \
        cpa16(st_ + OFF_KH + so_, Kh_ + go_); \
        cpa16(st_ + OFF_KL + so_, Kl_ + go_); \
        cpa16(st_ + OFF_VH + so_, Vh_ + go_); \
        cpa16(st_ + OFF_VL + so_, Vl_ + go_); \
    } \
    if (tid < 16) cpa16(st_ + OFF_MSK + tid * 16, mrow + (tile) * AK + tid * 4); \
    asm volatile("cp.async.commit_group;" ::: "memory"); \
} while (0)

    {
#pragma unroll
        for (int i = 0; i < 4; i++) {
            int idx = tid + i * 256, r = idx >> 3, c = idx & 7;
            size_t go = base + (size_t)(q0 + r) * HD + c * 8;
            cpa16(sb + SM_QH + r * 144 + c * 16, Qh_ + go);
            cpa16(sb + SM_QL + r * 144 + c * 16, Ql_ + go);
        }
        A_ISSUE(0, 0);   // group includes Q
    }
    A_ISSUE(1, 1);
    A_ISSUE(2, 2);

    asm volatile("cp.async.wait_group 2;" ::: "memory");
    __syncthreads();

    uint32_t qh[4][4], ql[4][4];
    {
        const int qrow = wid * 16 + (lane & 15);
        const int qc = (lane >> 4) * 8;
#pragma unroll
        for (int kf = 0; kf < 4; kf++) {
            uint32_t a = sb + SM_QH + qrow * 144 + (kf * 16 + qc) * 2;
            ldsm_x4(qh[kf], a);
            ldsm_x4(ql[kf], a + (SM_QL - SM_QH));
        }
    }

    float O[8][4];
#pragma unroll
    for (int i = 0; i < 8; i++)
#pragma unroll
        for (int j = 0; j < 4; j++) O[i][j] = 0.f;
    float mrun0 = -1e30f, mrun1 = -1e30f, lrun0 = 0.f, lrun1 = 0.f;

    const int kc2 = (lane & 3) * 2;
    const int krow = ((lane >> 4) & 1) * 8 + (lane & 7);
    const int kcol = ((lane >> 3) & 1) * 8;
    const int vrow = ((lane >> 3) & 1) * 8 + (lane & 7);
    const int vcol = ((lane >> 4) & 1) * 8;

    for (int t = 0; t < NT_K; t++) {
        const int stg = t & 3;
        if (t > 0) {
            if (t + 2 < NT_K) asm volatile("cp.async.wait_group 2;" ::: "memory");
            else if (t + 1 < NT_K) asm volatile("cp.async.wait_group 1;" ::: "memory");
            else asm volatile("cp.async.wait_group 0;" ::: "memory");
            __syncthreads();
        }
        if (t + 3 < NT_K) A_ISSUE(t + 3, (t + 3) & 3);

        const uint32_t st = sb + SM_ST0 + stg * ST_STRIDE;
        const char* stc = sm + SM_ST0 + stg * ST_STRIDE;

        // ---- S = Qh*Kh + Qh*Kl + Ql*Kh ----
        float S[8][4];
#pragma unroll
        for (int i = 0; i < 8; i++)
#pragma unroll
            for (int j = 0; j < 4; j++) S[i][j] = 0.f;

#pragma unroll
        for (int kf = 0; kf < 4; kf++) {
            uint32_t kb[4][4], klr[4][4];
#pragma unroll
            for (int np = 0; np < 4; np++) {
                uint32_t a = st + OFF_KH + (np * 16 + krow) * 144 + (kf * 16 + kcol) * 2;
                ldsm_x4(kb[np], a);
                ldsm_x4(klr[np], a + (OFF_KL - OFF_KH));
            }
#pragma unroll
            for (int np = 0; np < 4; np++) {
                mma16816(S[2 * np],     qh[kf], &kb[np][0]);
                mma16816(S[2 * np],     qh[kf], &klr[np][0]);
                mma16816(S[2 * np],     ql[kf], &kb[np][0]);
                mma16816(S[2 * np + 1], qh[kf], &kb[np][2]);
                mma16816(S[2 * np + 1], qh[kf], &klr[np][2]);
                mma16816(S[2 * np + 1], ql[kf], &kb[np][2]);
            }
        }

        // ---- mask + online softmax ----
        float tmax0 = -1e30f, tmax1 = -1e30f;
#pragma unroll
        for (int nt = 0; nt < 8; nt++) {
            const int k = nt * 8 + kc2;
            const int m0 = *(const int*)(stc + OFF_MSK + k * 4);
            const int m1 = *(const int*)(stc + OFF_MSK + k * 4 + 4);
            if (m0) { S[nt][0] = -CUDART_INF_F; S[nt][2] = -CUDART_INF_F; }
            if (m1) { S[nt][1] = -CUDART_INF_F; S[nt][3] = -CUDART_INF_F; }
            tmax0 = fmaxf(tmax0, fmaxf(S[nt][0], S[nt][1]));
            tmax1 = fmaxf(tmax1, fmaxf(S[nt][2], S[nt][3]));
        }
        tmax0 = fmaxf(tmax0, __shfl_xor_sync(0xFFFFFFFF, tmax0, 1));
        tmax0 = fmaxf(tmax0, __shfl_xor_sync(0xFFFFFFFF, tmax0, 2));
        tmax1 = fmaxf(tmax1, __shfl_xor_sync(0xFFFFFFFF, tmax1, 1));
        tmax1 = fmaxf(tmax1, __shfl_xor_sync(0xFFFFFFFF, tmax1, 2));

        const float mn0 = fmaxf(mrun0, tmax0);
        const float mn1 = fmaxf(mrun1, tmax1);
        const float sc0 = __expf(mrun0 - mn0);
        const float sc1 = __expf(mrun1 - mn1);
        mrun0 = mn0; mrun1 = mn1;

        float ts0 = 0.f, ts1 = 0.f;
        uint32_t ph[8][2], pl[8][2];
#pragma unroll
        for (int nt = 0; nt < 8; nt++) {
            const float p0 = __expf(S[nt][0] - mn0);
            const float p1 = __expf(S[nt][1] - mn0);
            const float p2 = __expf(S[nt][2] - mn1);
            const float p3 = __expf(S[nt][3] - mn1);
            ts0 += p0 + p1; ts1 += p2 + p3;
            split_pack(p0, p1, ph[nt][0], pl[nt][0]);
            split_pack(p2, p3, ph[nt][1], pl[nt][1]);
        }
        ts0 += __shfl_xor_sync(0xFFFFFFFF, ts0, 1);
        ts0 += __shfl_xor_sync(0xFFFFFFFF, ts0, 2);
        ts1 += __shfl_xor_sync(0xFFFFFFFF, ts1, 1);
        ts1 += __shfl_xor_sync(0xFFFFFFFF, ts1, 2);
        lrun0 = lrun0 * sc0 + ts0;
        lrun1 = lrun1 * sc1 + ts1;
#pragma unroll
        for (int nt = 0; nt < 8; nt++) {
            O[nt][0] *= sc0; O[nt][1] *= sc0;
            O[nt][2] *= sc1; O[nt][3] *= sc1;
        }

        // ---- O += Ph*Vh + Ph*Vl + Pl*Vh ----
#pragma unroll
        for (int kf = 0; kf < 4; kf++) {
            uint32_t ah[4] = {ph[2 * kf][0], ph[2 * kf][1], ph[2 * kf + 1][0], ph[2 * kf + 1][1]};
            uint32_t al[4] = {pl[2 * kf][0], pl[2 * kf][1], pl[2 * kf + 1][0], pl[2 * kf + 1][1]};
            uint32_t vb[4][4], vlr[4][4];
#pragma unroll
            for (int np = 0; np < 4; np++) {
                uint32_t a = st + OFF_VH + (kf * 16 + vrow) * 144 + (np * 16 + vcol) * 2;
                ldsm_x4t(vb[np], a);
                ldsm_x4t(vlr[np], a + (OFF_VL - OFF_VH));
            }
#pragma unroll
            for (int np = 0; np < 4; np++) {
                mma16816(O[2 * np],     ah, &vb[np][0]);
                mma16816(O[2 * np],     ah, &vlr[np][0]);
                mma16816(O[2 * np],     al, &vb[np][0]);
                mma16816(O[2 * np + 1], ah, &vb[np][2]);
                mma16816(O[2 * np + 1], ah, &vlr[np][2]);
                mma16816(O[2 * np + 1], al, &vb[np][2]);
            }
        }
        __syncthreads();
    }

    // ---- epilogue ----
    const float inv0 = 1.f / lrun0;
    const float inv1 = 1.f / lrun1;
    const int g = lane >> 2;
    const size_t row0 = (size_t)(b * SEQ + q0 + wid * 16 + g) * DIM + h * HD;
    const size_t row1 = row0 + (size_t)8 * DIM;
#pragma unroll
    for (int nt = 0; nt < 8; nt++) {
        const int col = nt * 8 + kc2;
        uint32_t hp, lp;
        split_pack(O[nt][0] * inv0, O[nt][1] * inv0, hp, lp);
        *(uint32_t*)&Oh_[row0 + col] = hp;
        *(uint32_t*)&Ol_[row0 + col] = lp;
        split_pack(O[nt][2] * inv1, O[nt][3] * inv1, hp, lp);
        *(uint32_t*)&Oh_[row1 + col] = hp;
        *(uint32_t*)&Ol_[row1 + col] = lp;
    }
}

// ---------------------------------------------------------------------------
// Launch
// ---------------------------------------------------------------------------
extern "C" void kernel_launch(void* const* d_in, const int* in_sizes, int n_in,
                              void* d_out, int out_size)
{
    const float* x  = (const float*)d_in[0];
    const int* mask = (const int*)d_in[1];
    const float* Wq = (const float*)d_in[2];
    const float* bq = (const float*)d_in[3];
    const float* Wk = (const float*)d_in[4];
    const float* bk = (const float*)d_in[5];
    const float* Wv = (const float*)d_in[6];
    const float* bv = (const float*)d_in[7];
    const float* Wo = (const float*)d_in[8];
    const float* bo = (const float*)d_in[9];
    float* out = (float*)d_out;

    __nv_bfloat16 *pqh, *pql, *pkh, *pkl, *pvh, *pvl;
    __nv_bfloat16 *pxh, *pxl, *pwh, *pwl, *poh, *pol;
    cudaGetSymbolAddress((void**)&pqh, g_qh);
    cudaGetSymbolAddress((void**)&pql, g_ql);
    cudaGetSymbolAddress((void**)&pkh, g_kh);
    cudaGetSymbolAddress((void**)&pkl, g_kl);
    cudaGetSymbolAddress((void**)&pvh, g_vh);
    cudaGetSymbolAddress((void**)&pvl, g_vl);
    cudaGetSymbolAddress((void**)&pxh, g_xh);
    cudaGetSymbolAddress((void**)&pxl, g_xl);
    cudaGetSymbolAddress((void**)&pwh, g_wh);
    cudaGetSymbolAddress((void**)&pwl, g_wl);
    cudaGetSymbolAddress((void**)&poh, g_oh);
    cudaGetSymbolAddress((void**)&pol, g_ol);

    cudaFuncSetAttribute(gemm_qkv, cudaFuncAttributeMaxDynamicSharedMemorySize, GEMM_SMEM);
    cudaFuncSetAttribute(gemm_out, cudaFuncAttributeMaxDynamicSharedMemorySize, GEMM_SMEM);
    cudaFuncSetAttribute(attn_mma, cudaFuncAttributeMaxDynamicSharedMemorySize, ATTN_SMEM);

    const int NW = DIM * DIM;

    split_kernel<<<1024, 256>>>(x,  pxh, pxl, NROWS * DIM / 4);
    split_kernel<<<512, 256>>>(Wq, pwh + 0 * NW, pwl + 0 * NW, NW / 4);
    split_kernel<<<512, 256>>>(Wk, pwh + 1 * NW, pwl + 1 * NW, NW / 4);
    split_kernel<<<512, 256>>>(Wv, pwh + 2 * NW, pwl + 2 * NW, NW / 4);
    split_kernel<<<512, 256>>>(Wo, pwh + 3 * NW, pwl + 3 * NW, NW / 4);

    dim3 qkvgrid(24, NROWS / BM);   // (24, 64)
    gemm_qkv<<<qkvgrid, 256, GEMM_SMEM>>>(pxh, pxl, pwh, pwl, bq, bk, bv,
                                          pqh, pql, pkh, pkl, pvh, pvl);

    dim3 agrid(SEQ / AQ, BATCH * HEADS);  // (16, 64)
    attn_mma<<<agrid, 256, ATTN_SMEM>>>(pqh, pql, pkh, pkl, pvh, pvl, mask, poh, pol);

    dim3 ogrid(DIM / BN, NROWS / BM);     // (8, 64)
    gemm_out<<<ogrid, 256, GEMM_SMEM>>>(poh, pol, pwh + 3 * NW, pwl + 3 * NW, bo, out);
}

// round 7
// speedup vs baseline: 3.7170x; 1.2529x over previous
#include <cuda_runtime.h>
#include <cuda_bf16.h>
#include <math_constants.h>
#include <cstdint>

// Problem constants
#define BATCH 4
#define SEQ   2048
#define DIM   1024
#define HEADS 16
#define HD    64
#define NROWS (BATCH * SEQ)   // 8192
#define QK_SCALE 0.125f

__device__ __forceinline__ uint32_t smem_u32(const void* p) {
    uint32_t a;
    asm("{ .reg .u64 t; cvta.to.shared.u64 t, %1; cvt.u32.u64 %0, t; }" : "=r"(a) : "l"(p));
    return a;
}
__device__ __forceinline__ void mma16816(float* d, const uint32_t* a, const uint32_t* b) {
    asm volatile("mma.sync.aligned.m16n8k16.row.col.f32.bf16.bf16.f32 "
        "{%0,%1,%2,%3}, {%4,%5,%6,%7}, {%8,%9}, {%0,%1,%2,%3};"
        : "+f"(d[0]), "+f"(d[1]), "+f"(d[2]), "+f"(d[3])
        : "r"(a[0]), "r"(a[1]), "r"(a[2]), "r"(a[3]), "r"(b[0]), "r"(b[1]));
}
__device__ __forceinline__ void ldsm_x4(uint32_t* r, uint32_t addr) {
    asm volatile("ldmatrix.sync.aligned.m8n8.x4.shared.b16 {%0,%1,%2,%3}, [%4];"
        : "=r"(r[0]), "=r"(r[1]), "=r"(r[2]), "=r"(r[3]) : "r"(addr));
}
__device__ __forceinline__ void ldsm_x4t(uint32_t* r, uint32_t addr) {
    asm volatile("ldmatrix.sync.aligned.m8n8.x4.trans.shared.b16 {%0,%1,%2,%3}, [%4];"
        : "=r"(r[0]), "=r"(r[1]), "=r"(r[2]), "=r"(r[3]) : "r"(addr));
}
__device__ __forceinline__ void cpa16(uint32_t s, const void* g) {
    asm volatile("cp.async.cg.shared.global [%0], [%1], 16;" :: "r"(s), "l"(g));
}
__device__ __forceinline__ void split_pack(float v0, float v1, uint32_t& hp, uint32_t& lp) {
    __nv_bfloat16 h0 = __float2bfloat16(v0), h1 = __float2bfloat16(v1);
    __nv_bfloat162 hh; hh.x = h0; hh.y = h1;
    hp = *reinterpret_cast<uint32_t*>(&hh);
    __nv_bfloat162 ll = __floats2bfloat162_rn(v0 - __bfloat162float(h0),
                                              v1 - __bfloat162float(h1));
    lp = *reinterpret_cast<uint32_t*>(&ll);
}

// ---------------------------------------------------------------------------
// Scratch
// ---------------------------------------------------------------------------
#define QKV_ELEMS (BATCH * HEADS * SEQ * HD)
__device__ __nv_bfloat16 g_qh[QKV_ELEMS];
__device__ __nv_bfloat16 g_ql[QKV_ELEMS];
__device__ __nv_bfloat16 g_kh[QKV_ELEMS];   // compacted along S
__device__ __nv_bfloat16 g_kl[QKV_ELEMS];
__device__ __nv_bfloat16 g_vh[QKV_ELEMS];
__device__ __nv_bfloat16 g_vl[QKV_ELEMS];
__device__ __nv_bfloat16 g_xh[NROWS * DIM];
__device__ __nv_bfloat16 g_xl[NROWS * DIM];
__device__ __nv_bfloat16 g_wh[4 * DIM * DIM];
__device__ __nv_bfloat16 g_wl[4 * DIM * DIM];
__device__ __nv_bfloat16 g_oh[NROWS * DIM];
__device__ __nv_bfloat16 g_ol[NROWS * DIM];
__device__ int g_prefix[BATCH * SEQ];   // compacted pos or -1
__device__ int g_cnt[BATCH];            // unmasked count per batch
__device__ int g_mc[BATCH * SEQ];       // compacted mask: 0 valid, 1 pad

// ---------------------------------------------------------------------------
// fp32 -> bf16 hi/lo split
// ---------------------------------------------------------------------------
struct bf4 { __nv_bfloat16 v[4]; };

__global__ void split_kernel(const float* __restrict__ src,
                             __nv_bfloat16* __restrict__ hi,
                             __nv_bfloat16* __restrict__ lo, int n4)
{
    for (int i = blockIdx.x * blockDim.x + threadIdx.x; i < n4; i += gridDim.x * blockDim.x) {
        float4 x = ((const float4*)src)[i];
        bf4 h, l;
        float f[4] = {x.x, x.y, x.z, x.w};
#pragma unroll
        for (int j = 0; j < 4; j++) {
            __nv_bfloat16 hv = __float2bfloat16(f[j]);
            h.v[j] = hv;
            l.v[j] = __float2bfloat16(f[j] - __bfloat162float(hv));
        }
        ((bf4*)hi)[i] = h;
        ((bf4*)lo)[i] = l;
    }
}

// ---------------------------------------------------------------------------
// Mask compaction: stable prefix scan per batch.
// ---------------------------------------------------------------------------
__global__ __launch_bounds__(256)
void compact_kernel(const int* __restrict__ mask,
                    int* __restrict__ prefix, int* __restrict__ cnt,
                    int* __restrict__ mc)
{
    __shared__ int cnts[256];
    __shared__ int offs[256];
    __shared__ int tot;
    const int b = blockIdx.x;
    const int t = threadIdx.x;
    const int* m = mask + b * SEQ;

    int c = 0;
#pragma unroll
    for (int j = 0; j < 8; j++) c += (m[t * 8 + j] == 0);
    cnts[t] = c;
    __syncthreads();
    if (t == 0) {
        int run = 0;
        for (int i = 0; i < 256; i++) { offs[i] = run; run += cnts[i]; }
        tot = run;
        cnt[b] = run;
    }
    __syncthreads();
    int o = offs[t];
#pragma unroll
    for (int j = 0; j < 8; j++) {
        const int s = t * 8 + j;
        if (m[s] == 0) { prefix[b * SEQ + s] = o; o++; }
        else           { prefix[b * SEQ + s] = -1; }
    }
    const int total = tot;
    for (int j = t; j < SEQ; j += 256) mc[b * SEQ + j] = (j < total) ? 0 : 1;
}

// Zero pad rows [cnt, ceil64(cnt)) of compacted K/V so tail tiles are clean.
__global__ __launch_bounds__(256)
void zeropad_kv(__nv_bfloat16* __restrict__ kh, __nv_bfloat16* __restrict__ kl,
                __nv_bfloat16* __restrict__ vh, __nv_bfloat16* __restrict__ vl,
                const int* __restrict__ cnt)
{
    const int bh = blockIdx.x;
    const int b = bh >> 4;
    const int c = cnt[b];
    const int pad = (c + 63) & ~63;
    const int nrows = pad - c;
    const size_t base = (size_t)bh * SEQ * HD;
    uint4 z; z.x = z.y = z.z = z.w = 0;
    for (int i = threadIdx.x; i < nrows * 8; i += 256) {
        const int r = c + (i >> 3);
        const int u = i & 7;
        const size_t o = base + (size_t)r * HD;
        ((uint4*)(kh + o))[u] = z;
        ((uint4*)(kl + o))[u] = z;
        ((uint4*)(vh + o))[u] = z;
        ((uint4*)(vl + o))[u] = z;
    }
}

// ---------------------------------------------------------------------------
// bf16x3 GEMM, 4-stage cp.async pipeline
// mode 0: bf16 hi/lo scatter [B,H,S,HD] by s (Q)
// mode 2: bf16 hi/lo scatter [B,H,S,HD] at compacted pos (K/V); masked skipped
// mode 1: fp32 row-major
// ---------------------------------------------------------------------------
#define BM 128
#define BN 128
#define BK 32
#define NKC (DIM / BK)
#define TILE_SB (128 * 80)
#define STAGE_SB (4 * TILE_SB)
#define NSTG 4
#define GEMM_SMEM (NSTG * STAGE_SB)

__device__ __forceinline__ void gemm_body(
    const __nv_bfloat16* Ahi, const __nv_bfloat16* Alo,
    const __nv_bfloat16* Whi, const __nv_bfloat16* Wlo,
    const float* bias, float* C,
    __nv_bfloat16* Chi, __nv_bfloat16* Clo,
    const int* prefix,
    int mode, float scale, int row0, int col0)
{
    extern __shared__ char smraw[];
    const uint32_t smem_base = smem_u32(smraw);

    const int tid = threadIdx.x;
    const int lane = tid & 31;
    const int wid = tid >> 5;
    const int wm = wid & 1;
    const int wn = wid >> 1;

    const uint4* srcs[4] = {(const uint4*)Ahi, (const uint4*)Alo,
                            (const uint4*)Whi, (const uint4*)Wlo};
    const int bases[4] = {row0, row0, col0, col0};

    float acc[4][4][4];
#pragma unroll
    for (int i = 0; i < 4; i++)
#pragma unroll
        for (int j = 0; j < 4; j++)
#pragma unroll
            for (int r = 0; r < 4; r++) acc[i][j][r] = 0.f;

    const int r0l = tid >> 2;
    const int cu  = tid & 3;

#define G_ISSUE(kc, buf) do { \
    uint32_t sb_ = smem_base + (buf) * STAGE_SB; \
    _Pragma("unroll") \
    for (int t_ = 0; t_ < 4; t_++) { \
        _Pragma("unroll") \
        for (int j_ = 0; j_ < 2; j_++) { \
            int r_ = r0l + j_ * 64; \
            const uint4* g_ = srcs[t_] + (size_t)(bases[t_] + r_) * 128 + (kc) * 4 + cu; \
            uint32_t s_ = sb_ + t_ * TILE_SB + r_ * 80 + cu * 16; \
            cpa16(s_, g_); \
        } \
    } \
    asm volatile("cp.async.commit_group;" ::: "memory"); \
} while (0)

    G_ISSUE(0, 0);
    G_ISSUE(1, 1);
    G_ISSUE(2, 2);

    for (int kc = 0; kc < NKC; kc++) {
        const int buf = kc & 3;
        asm volatile("cp.async.wait_group 2;" ::: "memory");
        __syncthreads();
        if (kc + 3 < NKC) G_ISSUE(kc + 3, (kc + 3) & 3);

        const uint32_t sb = smem_base + buf * STAGE_SB;
#pragma unroll
        for (int s = 0; s < 2; s++) {
            uint32_t a_h[4][4], a_l[4][4];
            const uint32_t acol = s * 32 + ((lane >> 4) << 4);
#pragma unroll
            for (int mt = 0; mt < 4; mt++) {
                const int r = wm * 64 + mt * 16 + (lane & 15);
                uint32_t addr = sb + r * 80 + acol;
                ldsm_x4(a_h[mt], addr);
                ldsm_x4(a_l[mt], addr + TILE_SB);
            }
            uint32_t b_h[4][2], b_l[4][2];
            const int mat = lane >> 3;
            const int mr = lane & 7;
            const uint32_t bcol = s * 32 + ((mat & 1) << 4);
#pragma unroll
            for (int np = 0; np < 2; np++) {
                const int n = wn * 32 + (np * 2 + (mat >> 1)) * 8 + mr;
                uint32_t addr = sb + 2 * TILE_SB + n * 80 + bcol;
                uint32_t q[4];
                ldsm_x4(q, addr);
                b_h[np * 2][0] = q[0]; b_h[np * 2][1] = q[1];
                b_h[np * 2 + 1][0] = q[2]; b_h[np * 2 + 1][1] = q[3];
                ldsm_x4(q, addr + TILE_SB);
                b_l[np * 2][0] = q[0]; b_l[np * 2][1] = q[1];
                b_l[np * 2 + 1][0] = q[2]; b_l[np * 2 + 1][1] = q[3];
            }
#pragma unroll
            for (int mt = 0; mt < 4; mt++)
#pragma unroll
                for (int nt = 0; nt < 4; nt++) {
                    mma16816(acc[mt][nt], a_h[mt], b_h[nt]);
                    mma16816(acc[mt][nt], a_h[mt], b_l[nt]);
                    mma16816(acc[mt][nt], a_l[mt], b_h[nt]);
                }
        }
    }

    const int g = lane >> 2;
    const int tg2 = (lane & 3) * 2;
#pragma unroll
    for (int mt = 0; mt < 4; mt++) {
#pragma unroll
        for (int hh = 0; hh < 2; hh++) {
            const int n = row0 + wm * 64 + mt * 16 + g + hh * 8;
            if (mode == 1) {
#pragma unroll
                for (int nt = 0; nt < 4; nt++) {
                    const int m = col0 + wn * 32 + nt * 8 + tg2;
                    float2 w;
                    w.x = acc[mt][nt][hh * 2 + 0] + bias[m];
                    w.y = acc[mt][nt][hh * 2 + 1] + bias[m + 1];
                    *(float2*)&C[(size_t)n * DIM + m] = w;
                }
            } else {
                const int b = n >> 11;
                int sq = n & (SEQ - 1);
                if (mode == 2) {
                    const int cp = prefix[(b << 11) + sq];
                    if (cp < 0) continue;
                    sq = cp;
                }
#pragma unroll
                for (int nt = 0; nt < 4; nt++) {
                    const int m = col0 + wn * 32 + nt * 8 + tg2;
                    const float v0 = (acc[mt][nt][hh * 2 + 0] + bias[m]) * scale;
                    const float v1 = (acc[mt][nt][hh * 2 + 1] + bias[m + 1]) * scale;
                    const int h = m >> 6;
                    const int hd = m & (HD - 1);
                    uint32_t hp, lp;
                    split_pack(v0, v1, hp, lp);
                    const size_t o = (((size_t)(b * HEADS + h) * SEQ) + sq) * HD + hd;
                    *(uint32_t*)&Chi[o] = hp;
                    *(uint32_t*)&Clo[o] = lp;
                }
            }
        }
    }
}

// Fused Q/K/V projection: grid (24, 64)
__global__ __launch_bounds__(256, 1)
void gemm_qkv(const __nv_bfloat16* __restrict__ xh, const __nv_bfloat16* __restrict__ xl,
              const __nv_bfloat16* __restrict__ wh, const __nv_bfloat16* __restrict__ wl,
              const float* __restrict__ bq, const float* __restrict__ bk,
              const float* __restrict__ bv, const int* __restrict__ prefix,
              __nv_bfloat16* __restrict__ qh, __nv_bfloat16* __restrict__ ql,
              __nv_bfloat16* __restrict__ kh, __nv_bfloat16* __restrict__ kl,
              __nv_bfloat16* __restrict__ vh, __nv_bfloat16* __restrict__ vl)
{
    const int w = blockIdx.x >> 3;
    const int col0 = (blockIdx.x & 7) * BN;
    const int row0 = blockIdx.y * BM;
    const int NW = DIM * DIM;
    const float* bias = (w == 0) ? bq : (w == 1) ? bk : bv;
    __nv_bfloat16* Chi = (w == 0) ? qh : (w == 1) ? kh : vh;
    __nv_bfloat16* Clo = (w == 0) ? ql : (w == 1) ? kl : vl;
    const float scale = (w == 0) ? QK_SCALE : 1.0f;
    const int mode = (w == 0) ? 0 : 2;
    gemm_body(xh, xl, wh + (size_t)w * NW, wl + (size_t)w * NW, bias,
              nullptr, Chi, Clo, prefix, mode, scale, row0, col0);
}

__global__ __launch_bounds__(256, 1)
void gemm_out(const __nv_bfloat16* __restrict__ oh, const __nv_bfloat16* __restrict__ ol,
              const __nv_bfloat16* __restrict__ wh, const __nv_bfloat16* __restrict__ wl,
              const float* __restrict__ bias, float* __restrict__ out)
{
    gemm_body(oh, ol, wh, wl, bias, out, nullptr, nullptr, nullptr, 1, 1.0f,
              blockIdx.y * BM, blockIdx.x * BN);
}

// ---------------------------------------------------------------------------
// MMA flash attention over compacted keys, dynamic tile count
// ---------------------------------------------------------------------------
#define AQ 128
#define AK 64
#define SM_QH 0
#define SM_QL 18432
#define SM_ST0 36864
#define ST_STRIDE 37120
#define OFF_KH 0
#define OFF_KL 9216
#define OFF_VH 18432
#define OFF_VL 27648
#define OFF_MSK 36864
#define A_NSTG 4
#define ATTN_SMEM (SM_ST0 + A_NSTG * ST_STRIDE)

__global__ __launch_bounds__(256, 1)
void attn_mma(const __nv_bfloat16* __restrict__ Qh_, const __nv_bfloat16* __restrict__ Ql_,
              const __nv_bfloat16* __restrict__ Kh_, const __nv_bfloat16* __restrict__ Kl_,
              const __nv_bfloat16* __restrict__ Vh_, const __nv_bfloat16* __restrict__ Vl_,
              const int* __restrict__ mc, const int* __restrict__ cntp,
              __nv_bfloat16* __restrict__ Oh_, __nv_bfloat16* __restrict__ Ol_)
{
    extern __shared__ char sm[];
    const uint32_t sb = smem_u32(sm);
    const int tid = threadIdx.x, lane = tid & 31, wid = tid >> 5;
    const int bh = blockIdx.y, b = bh >> 4, h = bh & 15;
    const int q0 = blockIdx.x * AQ;
    const size_t base = (size_t)bh * SEQ * HD;
    const int* mrow = mc + b * SEQ;
    const int nt = (cntp[b] + AK - 1) >> 6;

#define A_ISSUE(tile, stage) do { \
    uint32_t st_ = sb + SM_ST0 + (stage) * ST_STRIDE; \
    _Pragma("unroll") \
    for (int i_ = 0; i_ < 2; i_++) { \
        int idx_ = tid + i_ * 256, r_ = idx_ >> 3, c_ = idx_ & 7; \
        size_t go_ = base + (size_t)((tile) * AK + r_) * HD + c_ * 8; \
        uint32_t so_ = r_ * 144 + c_ * 16; \
        cpa16(st_ + OFF_KH + so_, Kh_ + go_); \
        cpa16(st_ + OFF_KL + so_, Kl_ + go_); \
        cpa16(st_ + OFF_VH + so_, Vh_ + go_); \
        cpa16(st_ + OFF_VL + so_, Vl_ + go_); \
    } \
    if (tid < 16) cpa16(st_ + OFF_MSK + tid * 16, mrow + (tile) * AK + tid * 4); \
    asm volatile("cp.async.commit_group;" ::: "memory"); \
} while (0)
#define A_EMPTY() asm volatile("cp.async.commit_group;" ::: "memory")

    {
#pragma unroll
        for (int i = 0; i < 4; i++) {
            int idx = tid + i * 256, r = idx >> 3, c = idx & 7;
            size_t go = base + (size_t)(q0 + r) * HD + c * 8;
            cpa16(sb + SM_QH + r * 144 + c * 16, Qh_ + go);
            cpa16(sb + SM_QL + r * 144 + c * 16, Ql_ + go);
        }
        A_ISSUE(0, 0);   // group 0 includes Q
    }
    if (nt > 1) A_ISSUE(1, 1); else A_EMPTY();
    if (nt > 2) A_ISSUE(2, 2); else A_EMPTY();

    asm volatile("cp.async.wait_group 2;" ::: "memory");
    __syncthreads();

    uint32_t qh[4][4], ql[4][4];
    {
        const int qrow = wid * 16 + (lane & 15);
        const int qc = (lane >> 4) * 8;
#pragma unroll
        for (int kf = 0; kf < 4; kf++) {
            uint32_t a = sb + SM_QH + qrow * 144 + (kf * 16 + qc) * 2;
            ldsm_x4(qh[kf], a);
            ldsm_x4(ql[kf], a + (SM_QL - SM_QH));
        }
    }

    float O[8][4];
#pragma unroll
    for (int i = 0; i < 8; i++)
#pragma unroll
        for (int j = 0; j < 4; j++) O[i][j] = 0.f;
    float mrun0 = -1e30f, mrun1 = -1e30f, lrun0 = 0.f, lrun1 = 0.f;

    const int kc2 = (lane & 3) * 2;
    const int krow = ((lane >> 4) & 1) * 8 + (lane & 7);
    const int kcol = ((lane >> 3) & 1) * 8;
    const int vrow = ((lane >> 3) & 1) * 8 + (lane & 7);
    const int vcol = ((lane >> 4) & 1) * 8;

    for (int t = 0; t < nt; t++) {
        const int stg = t & 3;
        if (t > 0) {
            asm volatile("cp.async.wait_group 2;" ::: "memory");
            __syncthreads();
        }
        if (t + 3 < nt) A_ISSUE(t + 3, (t + 3) & 3); else A_EMPTY();

        const uint32_t st = sb + SM_ST0 + stg * ST_STRIDE;
        const char* stc = sm + SM_ST0 + stg * ST_STRIDE;

        // ---- S = Qh*Kh + Qh*Kl + Ql*Kh ----
        float S[8][4];
#pragma unroll
        for (int i = 0; i < 8; i++)
#pragma unroll
            for (int j = 0; j < 4; j++) S[i][j] = 0.f;

#pragma unroll
        for (int kf = 0; kf < 4; kf++) {
            uint32_t kb[4][4], klr[4][4];
#pragma unroll
            for (int np = 0; np < 4; np++) {
                uint32_t a = st + OFF_KH + (np * 16 + krow) * 144 + (kf * 16 + kcol) * 2;
                ldsm_x4(kb[np], a);
                ldsm_x4(klr[np], a + (OFF_KL - OFF_KH));
            }
#pragma unroll
            for (int np = 0; np < 4; np++) {
                mma16816(S[2 * np],     qh[kf], &kb[np][0]);
                mma16816(S[2 * np],     qh[kf], &klr[np][0]);
                mma16816(S[2 * np],     ql[kf], &kb[np][0]);
                mma16816(S[2 * np + 1], qh[kf], &kb[np][2]);
                mma16816(S[2 * np + 1], qh[kf], &klr[np][2]);
                mma16816(S[2 * np + 1], ql[kf], &kb[np][2]);
            }
        }

        // ---- mask + online softmax ----
        float tmax0 = -1e30f, tmax1 = -1e30f;
#pragma unroll
        for (int nti = 0; nti < 8; nti++) {
            const int k = nti * 8 + kc2;
            const int m0 = *(const int*)(stc + OFF_MSK + k * 4);
            const int m1 = *(const int*)(stc + OFF_MSK + k * 4 + 4);
            if (m0) { S[nti][0] = -CUDART_INF_F; S[nti][2] = -CUDART_INF_F; }
            if (m1) { S[nti][1] = -CUDART_INF_F; S[nti][3] = -CUDART_INF_F; }
            tmax0 = fmaxf(tmax0, fmaxf(S[nti][0], S[nti][1]));
            tmax1 = fmaxf(tmax1, fmaxf(S[nti][2], S[nti][3]));
        }
        tmax0 = fmaxf(tmax0, __shfl_xor_sync(0xFFFFFFFF, tmax0, 1));
        tmax0 = fmaxf(tmax0, __shfl_xor_sync(0xFFFFFFFF, tmax0, 2));
        tmax1 = fmaxf(tmax1, __shfl_xor_sync(0xFFFFFFFF, tmax1, 1));
        tmax1 = fmaxf(tmax1, __shfl_xor_sync(0xFFFFFFFF, tmax1, 2));

        const float mn0 = fmaxf(mrun0, tmax0);
        const float mn1 = fmaxf(mrun1, tmax1);
        const float sc0 = __expf(mrun0 - mn0);
        const float sc1 = __expf(mrun1 - mn1);
        mrun0 = mn0; mrun1 = mn1;

        float ts0 = 0.f, ts1 = 0.f;
        uint32_t ph[8][2], pl[8][2];
#pragma unroll
        for (int nti = 0; nti < 8; nti++) {
            const float p0 = __expf(S[nti][0] - mn0);
            const float p1 = __expf(S[nti][1] - mn0);
            const float p2 = __expf(S[nti][2] - mn1);
            const float p3 = __expf(S[nti][3] - mn1);
            ts0 += p0 + p1; ts1 += p2 + p3;
            split_pack(p0, p1, ph[nti][0], pl[nti][0]);
            split_pack(p2, p3, ph[nti][1], pl[nti][1]);
        }
        ts0 += __shfl_xor_sync(0xFFFFFFFF, ts0, 1);
        ts0 += __shfl_xor_sync(0xFFFFFFFF, ts0, 2);
        ts1 += __shfl_xor_sync(0xFFFFFFFF, ts1, 1);
        ts1 += __shfl_xor_sync(0xFFFFFFFF, ts1, 2);
        lrun0 = lrun0 * sc0 + ts0;
        lrun1 = lrun1 * sc1 + ts1;
#pragma unroll
        for (int nti = 0; nti < 8; nti++) {
            O[nti][0] *= sc0; O[nti][1] *= sc0;
            O[nti][2] *= sc1; O[nti][3] *= sc1;
        }

        // ---- O += Ph*Vh + Ph*Vl + Pl*Vh ----
#pragma unroll
        for (int kf = 0; kf < 4; kf++) {
            uint32_t ah[4] = {ph[2 * kf][0], ph[2 * kf][1], ph[2 * kf + 1][0], ph[2 * kf + 1][1]};
            uint32_t al[4] = {pl[2 * kf][0], pl[2 * kf][1], pl[2 * kf + 1][0], pl[2 * kf + 1][1]};
            uint32_t vb[4][4], vlr[4][4];
#pragma unroll
            for (int np = 0; np < 4; np++) {
                uint32_t a = st + OFF_VH + (kf * 16 + vrow) * 144 + (np * 16 + vcol) * 2;
                ldsm_x4t(vb[np], a);
                ldsm_x4t(vlr[np], a + (OFF_VL - OFF_VH));
            }
#pragma unroll
            for (int np = 0; np < 4; np++) {
                mma16816(O[2 * np],     ah, &vb[np][0]);
                mma16816(O[2 * np],     ah, &vlr[np][0]);
                mma16816(O[2 * np],     al, &vb[np][0]);
                mma16816(O[2 * np + 1], ah, &vb[np][2]);
                mma16816(O[2 * np + 1], ah, &vlr[np][2]);
                mma16816(O[2 * np + 1], al, &vb[np][2]);
            }
        }
    }

    // ---- epilogue ----
    const float inv0 = 1.f / lrun0;
    const float inv1 = 1.f / lrun1;
    const int g = lane >> 2;
    const size_t row0 = (size_t)(b * SEQ + q0 + wid * 16 + g) * DIM + h * HD;
    const size_t row1 = row0 + (size_t)8 * DIM;
#pragma unroll
    for (int nti = 0; nti < 8; nti++) {
        const int col = nti * 8 + kc2;
        uint32_t hp, lp;
        split_pack(O[nti][0] * inv0, O[nti][1] * inv0, hp, lp);
        *(uint32_t*)&Oh_[row0 + col] = hp;
        *(uint32_t*)&Ol_[row0 + col] = lp;
        split_pack(O[nti][2] * inv1, O[nti][3] * inv1, hp, lp);
        *(uint32_t*)&Oh_[row1 + col] = hp;
        *(uint32_t*)&Ol_[row1 + col] = lp;
    }
}

// ---------------------------------------------------------------------------
// Launch
// ---------------------------------------------------------------------------
extern "C" void kernel_launch(void* const* d_in, const int* in_sizes, int n_in,
                              void* d_out, int out_size)
{
    const float* x  = (const float*)d_in[0];
    const int* mask = (const int*)d_in[1];
    const float* Wq = (const float*)d_in[2];
    const float* bq = (const float*)d_in[3];
    const float* Wk = (const float*)d_in[4];
    const float* bk = (const float*)d_in[5];
    const float* Wv = (const float*)d_in[6];
    const float* bv = (const float*)d_in[7];
    const float* Wo = (const float*)d_in[8];
    const float* bo = (const float*)d_in[9];
    float* out = (float*)d_out;

    __nv_bfloat16 *pqh, *pql, *pkh, *pkl, *pvh, *pvl;
    __nv_bfloat16 *pxh, *pxl, *pwh, *pwl, *poh, *pol;
    int *ppre, *pcnt, *pmc;
    cudaGetSymbolAddress((void**)&pqh, g_qh);
    cudaGetSymbolAddress((void**)&pql, g_ql);
    cudaGetSymbolAddress((void**)&pkh, g_kh);
    cudaGetSymbolAddress((void**)&pkl, g_kl);
    cudaGetSymbolAddress((void**)&pvh, g_vh);
    cudaGetSymbolAddress((void**)&pvl, g_vl);
    cudaGetSymbolAddress((void**)&pxh, g_xh);
    cudaGetSymbolAddress((void**)&pxl, g_xl);
    cudaGetSymbolAddress((void**)&pwh, g_wh);
    cudaGetSymbolAddress((void**)&pwl, g_wl);
    cudaGetSymbolAddress((void**)&poh, g_oh);
    cudaGetSymbolAddress((void**)&pol, g_ol);
    cudaGetSymbolAddress((void**)&ppre, g_prefix);
    cudaGetSymbolAddress((void**)&pcnt, g_cnt);
    cudaGetSymbolAddress((void**)&pmc, g_mc);

    cudaFuncSetAttribute(gemm_qkv, cudaFuncAttributeMaxDynamicSharedMemorySize, GEMM_SMEM);
    cudaFuncSetAttribute(gemm_out, cudaFuncAttributeMaxDynamicSharedMemorySize, GEMM_SMEM);
    cudaFuncSetAttribute(attn_mma, cudaFuncAttributeMaxDynamicSharedMemorySize, ATTN_SMEM);

    const int NW = DIM * DIM;

    split_kernel<<<1024, 256>>>(x,  pxh, pxl, NROWS * DIM / 4);
    split_kernel<<<512, 256>>>(Wq, pwh + 0 * NW, pwl + 0 * NW, NW / 4);
    split_kernel<<<512, 256>>>(Wk, pwh + 1 * NW, pwl + 1 * NW, NW / 4);
    split_kernel<<<512, 256>>>(Wv, pwh + 2 * NW, pwl + 2 * NW, NW / 4);
    split_kernel<<<512, 256>>>(Wo, pwh + 3 * NW, pwl + 3 * NW, NW / 4);

    compact_kernel<<<BATCH, 256>>>(mask, ppre, pcnt, pmc);
    zeropad_kv<<<BATCH * HEADS, 256>>>(pkh, pkl, pvh, pvl, pcnt);

    dim3 qkvgrid(24, NROWS / BM);
    gemm_qkv<<<qkvgrid, 256, GEMM_SMEM>>>(pxh, pxl, pwh, pwl, bq, bk, bv, ppre,
                                          pqh, pql, pkh, pkl, pvh, pvl);

    dim3 agrid(SEQ / AQ, BATCH * HEADS);
    attn_mma<<<agrid, 256, ATTN_SMEM>>>(pqh, pql, pkh, pkl, pvh, pvl, pmc, pcnt, poh, pol);

    dim3 ogrid(DIM / BN, NROWS / BM);
    gemm_out<<<ogrid, 256, GEMM_SMEM>>>(poh, pol, pwh + 3 * NW, pwl + 3 * NW, bo, out);
}

// round 8
// speedup vs baseline: 4.5467x; 1.2232x over previous
#include <cuda_runtime.h>
#include <cuda_bf16.h>
#include <math_constants.h>
#include <cstdint>

// Problem constants
#define BATCH 4
#define SEQ   2048
#define DIM   1024
#define HEADS 16
#define HD    64
#define NROWS (BATCH * SEQ)   // 8192
#define QK_SCALE 0.125f

__device__ __forceinline__ uint32_t smem_u32(const void* p) {
    uint32_t a;
    asm("{ .reg .u64 t; cvta.to.shared.u64 t, %1; cvt.u32.u64 %0, t; }" : "=r"(a) : "l"(p));
    return a;
}
__device__ __forceinline__ void mma16816(float* d, const uint32_t* a, const uint32_t* b) {
    asm volatile("mma.sync.aligned.m16n8k16.row.col.f32.bf16.bf16.f32 "
        "{%0,%1,%2,%3}, {%4,%5,%6,%7}, {%8,%9}, {%0,%1,%2,%3};"
        : "+f"(d[0]), "+f"(d[1]), "+f"(d[2]), "+f"(d[3])
        : "r"(a[0]), "r"(a[1]), "r"(a[2]), "r"(a[3]), "r"(b[0]), "r"(b[1]));
}
__device__ __forceinline__ void ldsm_x4(uint32_t* r, uint32_t addr) {
    asm volatile("ldmatrix.sync.aligned.m8n8.x4.shared.b16 {%0,%1,%2,%3}, [%4];"
        : "=r"(r[0]), "=r"(r[1]), "=r"(r[2]), "=r"(r[3]) : "r"(addr));
}
__device__ __forceinline__ void ldsm_x4t(uint32_t* r, uint32_t addr) {
    asm volatile("ldmatrix.sync.aligned.m8n8.x4.trans.shared.b16 {%0,%1,%2,%3}, [%4];"
        : "=r"(r[0]), "=r"(r[1]), "=r"(r[2]), "=r"(r[3]) : "r"(addr));
}
__device__ __forceinline__ void cpa16(uint32_t s, const void* g) {
    asm volatile("cp.async.cg.shared.global [%0], [%1], 16;" :: "r"(s), "l"(g));
}
__device__ __forceinline__ void split_pack(float v0, float v1, uint32_t& hp, uint32_t& lp) {
    __nv_bfloat16 h0 = __float2bfloat16(v0), h1 = __float2bfloat16(v1);
    __nv_bfloat162 hh; hh.x = h0; hh.y = h1;
    hp = *reinterpret_cast<uint32_t*>(&hh);
    __nv_bfloat162 ll = __floats2bfloat162_rn(v0 - __bfloat162float(h0),
                                              v1 - __bfloat162float(h1));
    lp = *reinterpret_cast<uint32_t*>(&ll);
}

// ---------------------------------------------------------------------------
// Scratch
// ---------------------------------------------------------------------------
#define QKV_ELEMS (BATCH * HEADS * SEQ * HD)
__device__ __nv_bfloat16 g_qh[QKV_ELEMS];
__device__ __nv_bfloat16 g_ql[QKV_ELEMS];
__device__ __nv_bfloat16 g_kh[QKV_ELEMS];   // compacted along S
__device__ __nv_bfloat16 g_kl[QKV_ELEMS];
__device__ __nv_bfloat16 g_vh[QKV_ELEMS];
__device__ __nv_bfloat16 g_vl[QKV_ELEMS];
__device__ __nv_bfloat16 g_xh[NROWS * DIM];
__device__ __nv_bfloat16 g_xl[NROWS * DIM];
__device__ __nv_bfloat16 g_wh[4 * DIM * DIM];
__device__ __nv_bfloat16 g_wl[4 * DIM * DIM];
__device__ __nv_bfloat16 g_oh[NROWS * DIM];
__device__ __nv_bfloat16 g_ol[NROWS * DIM];
__device__ int g_gather[BATCH * SEQ];   // compacted pos -> source s
__device__ int g_cnt[BATCH];            // unmasked count per batch
__device__ int g_mc[BATCH * SEQ];       // compacted mask: 0 valid, 1 pad

// ---------------------------------------------------------------------------
// fp32 -> bf16 hi/lo split
// ---------------------------------------------------------------------------
struct bf4 { __nv_bfloat16 v[4]; };

__global__ void split_kernel(const float* __restrict__ src,
                             __nv_bfloat16* __restrict__ hi,
                             __nv_bfloat16* __restrict__ lo, int n4)
{
    for (int i = blockIdx.x * blockDim.x + threadIdx.x; i < n4; i += gridDim.x * blockDim.x) {
        float4 x = ((const float4*)src)[i];
        bf4 h, l;
        float f[4] = {x.x, x.y, x.z, x.w};
#pragma unroll
        for (int j = 0; j < 4; j++) {
            __nv_bfloat16 hv = __float2bfloat16(f[j]);
            h.v[j] = hv;
            l.v[j] = __float2bfloat16(f[j] - __bfloat162float(hv));
        }
        ((bf4*)hi)[i] = h;
        ((bf4*)lo)[i] = l;
    }
}

// ---------------------------------------------------------------------------
// Mask compaction: stable scan; emits gather list, count, compacted mask.
// ---------------------------------------------------------------------------
__global__ __launch_bounds__(256)
void compact_kernel(const int* __restrict__ mask,
                    int* __restrict__ gather, int* __restrict__ cnt,
                    int* __restrict__ mc)
{
    __shared__ int cnts[256];
    __shared__ int offs[256];
    __shared__ int tot;
    const int b = blockIdx.x;
    const int t = threadIdx.x;
    const int* m = mask + b * SEQ;

    int c = 0;
#pragma unroll
    for (int j = 0; j < 8; j++) c += (m[t * 8 + j] == 0);
    cnts[t] = c;
    __syncthreads();
    if (t == 0) {
        int run = 0;
        for (int i = 0; i < 256; i++) { offs[i] = run; run += cnts[i]; }
        tot = run;
        cnt[b] = run;
    }
    __syncthreads();
    int o = offs[t];
#pragma unroll
    for (int j = 0; j < 8; j++) {
        const int s = t * 8 + j;
        if (m[s] == 0) { gather[b * SEQ + o] = s; o++; }
    }
    const int total = tot;
    for (int j = t; j < SEQ; j += 256) mc[b * SEQ + j] = (j < total) ? 0 : 1;
}

// Zero pad rows [cnt, ceil64(cnt)) of compacted K/V.
__global__ __launch_bounds__(256)
void zeropad_kv(__nv_bfloat16* __restrict__ kh, __nv_bfloat16* __restrict__ kl,
                __nv_bfloat16* __restrict__ vh, __nv_bfloat16* __restrict__ vl,
                const int* __restrict__ cnt)
{
    const int bh = blockIdx.x;
    const int b = bh >> 4;
    const int c = cnt[b];
    const int pad = (c + 63) & ~63;
    const int nrows = pad - c;
    const size_t base = (size_t)bh * SEQ * HD;
    uint4 z; z.x = z.y = z.z = z.w = 0;
    for (int i = threadIdx.x; i < nrows * 8; i += 256) {
        const int r = c + (i >> 3);
        const int u = i & 7;
        const size_t o = base + (size_t)r * HD;
        ((uint4*)(kh + o))[u] = z;
        ((uint4*)(kl + o))[u] = z;
        ((uint4*)(vh + o))[u] = z;
        ((uint4*)(vl + o))[u] = z;
    }
}

// ---------------------------------------------------------------------------
// bf16x3 GEMM, 4-stage cp.async pipeline
// mode 0: bf16 hi/lo scatter [B,H,S,HD] by s (Q)
// mode 2: A rows gathered from compacted space; store at compacted row (K/V)
// mode 1: fp32 row-major
// ---------------------------------------------------------------------------
#define BM 128
#define BN 128
#define BK 32
#define NKC (DIM / BK)
#define TILE_SB (128 * 80)
#define STAGE_SB (4 * TILE_SB)
#define NSTG 4
#define GEMM_SMEM (NSTG * STAGE_SB)

__device__ __forceinline__ void gemm_body(
    const __nv_bfloat16* Ahi, const __nv_bfloat16* Alo,
    const __nv_bfloat16* Whi, const __nv_bfloat16* Wlo,
    const float* bias, float* C,
    __nv_bfloat16* Chi, __nv_bfloat16* Clo,
    const int* gather, const int* cntp,
    int mode, float scale, int row0, int col0)
{
    extern __shared__ char smraw[];
    const uint32_t smem_base = smem_u32(smraw);

    const int tid = threadIdx.x;
    const int lane = tid & 31;
    const int wid = tid >> 5;
    const int wm = wid & 1;
    const int wn = wid >> 1;

    int cntb = 0;
    if (mode == 2) {
        const int b = row0 >> 11;
        cntb = cntp[b];
        if ((row0 & (SEQ - 1)) >= cntb) return;   // whole block past count
    }

    float acc[4][4][4];
#pragma unroll
    for (int i = 0; i < 4; i++)
#pragma unroll
        for (int j = 0; j < 4; j++)
#pragma unroll
            for (int r = 0; r < 4; r++) acc[i][j][r] = 0.f;

    const int r0l = tid >> 2;
    const int cu  = tid & 3;

    // per-thread source row pointers (constant across k-chunks)
    const uint4* aptr[2][2];
    const uint4* wptr[2][2];
#pragma unroll
    for (int j = 0; j < 2; j++) {
        const int r = r0l + j * 64;
        int srcA;
        if (mode == 2) {
            const int n = row0 + r;
            const int b = n >> 11;
            int i = n & (SEQ - 1);
            if (i >= cntb) i = cntb - 1;        // clamp (results discarded)
            srcA = (b << 11) + gather[(b << 11) + i];
        } else {
            srcA = row0 + r;
        }
        aptr[j][0] = (const uint4*)Ahi + (size_t)srcA * 128 + cu;
        aptr[j][1] = (const uint4*)Alo + (size_t)srcA * 128 + cu;
        wptr[j][0] = (const uint4*)Whi + (size_t)(col0 + r) * 128 + cu;
        wptr[j][1] = (const uint4*)Wlo + (size_t)(col0 + r) * 128 + cu;
    }

#define G_ISSUE(kc, buf) do { \
    uint32_t sb_ = smem_base + (buf) * STAGE_SB; \
    _Pragma("unroll") \
    for (int j_ = 0; j_ < 2; j_++) { \
        const int r_ = r0l + j_ * 64; \
        const uint32_t so_ = r_ * 80 + cu * 16; \
        cpa16(sb_ + 0 * TILE_SB + so_, aptr[j_][0] + (kc) * 4); \
        cpa16(sb_ + 1 * TILE_SB + so_, aptr[j_][1] + (kc) * 4); \
        cpa16(sb_ + 2 * TILE_SB + so_, wptr[j_][0] + (kc) * 4); \
        cpa16(sb_ + 3 * TILE_SB + so_, wptr[j_][1] + (kc) * 4); \
    } \
    asm volatile("cp.async.commit_group;" ::: "memory"); \
} while (0)

    G_ISSUE(0, 0);
    G_ISSUE(1, 1);
    G_ISSUE(2, 2);

    for (int kc = 0; kc < NKC; kc++) {
        const int buf = kc & 3;
        asm volatile("cp.async.wait_group 2;" ::: "memory");
        __syncthreads();
        if (kc + 3 < NKC) G_ISSUE(kc + 3, (kc + 3) & 3);

        const uint32_t sb = smem_base + buf * STAGE_SB;
#pragma unroll
        for (int s = 0; s < 2; s++) {
            uint32_t a_h[4][4], a_l[4][4];
            const uint32_t acol = s * 32 + ((lane >> 4) << 4);
#pragma unroll
            for (int mt = 0; mt < 4; mt++) {
                const int r = wm * 64 + mt * 16 + (lane & 15);
                uint32_t addr = sb + r * 80 + acol;
                ldsm_x4(a_h[mt], addr);
                ldsm_x4(a_l[mt], addr + TILE_SB);
            }
            uint32_t b_h[4][2], b_l[4][2];
            const int mat = lane >> 3;
            const int mr = lane & 7;
            const uint32_t bcol = s * 32 + ((mat & 1) << 4);
#pragma unroll
            for (int np = 0; np < 2; np++) {
                const int n = wn * 32 + (np * 2 + (mat >> 1)) * 8 + mr;
                uint32_t addr = sb + 2 * TILE_SB + n * 80 + bcol;
                uint32_t q[4];
                ldsm_x4(q, addr);
                b_h[np * 2][0] = q[0]; b_h[np * 2][1] = q[1];
                b_h[np * 2 + 1][0] = q[2]; b_h[np * 2 + 1][1] = q[3];
                ldsm_x4(q, addr + TILE_SB);
                b_l[np * 2][0] = q[0]; b_l[np * 2][1] = q[1];
                b_l[np * 2 + 1][0] = q[2]; b_l[np * 2 + 1][1] = q[3];
            }
#pragma unroll
            for (int mt = 0; mt < 4; mt++)
#pragma unroll
                for (int nt = 0; nt < 4; nt++) {
                    mma16816(acc[mt][nt], a_h[mt], b_h[nt]);
                    mma16816(acc[mt][nt], a_h[mt], b_l[nt]);
                    mma16816(acc[mt][nt], a_l[mt], b_h[nt]);
                }
        }
    }

    const int g = lane >> 2;
    const int tg2 = (lane & 3) * 2;
#pragma unroll
    for (int mt = 0; mt < 4; mt++) {
#pragma unroll
        for (int hh = 0; hh < 2; hh++) {
            const int n = row0 + wm * 64 + mt * 16 + g + hh * 8;
            if (mode == 1) {
#pragma unroll
                for (int nt = 0; nt < 4; nt++) {
                    const int m = col0 + wn * 32 + nt * 8 + tg2;
                    float2 w;
                    w.x = acc[mt][nt][hh * 2 + 0] + bias[m];
                    w.y = acc[mt][nt][hh * 2 + 1] + bias[m + 1];
                    *(float2*)&C[(size_t)n * DIM + m] = w;
                }
            } else {
                const int b = n >> 11;
                const int sq = n & (SEQ - 1);
                if (mode == 2 && sq >= cntb) continue;
#pragma unroll
                for (int nt = 0; nt < 4; nt++) {
                    const int m = col0 + wn * 32 + nt * 8 + tg2;
                    const float v0 = (acc[mt][nt][hh * 2 + 0] + bias[m]) * scale;
                    const float v1 = (acc[mt][nt][hh * 2 + 1] + bias[m + 1]) * scale;
                    const int h = m >> 6;
                    const int hd = m & (HD - 1);
                    uint32_t hp, lp;
                    split_pack(v0, v1, hp, lp);
                    const size_t o = (((size_t)(b * HEADS + h) * SEQ) + sq) * HD + hd;
                    *(uint32_t*)&Chi[o] = hp;
                    *(uint32_t*)&Clo[o] = lp;
                }
            }
        }
    }
}

// Fused Q/K/V projection: grid (24, 64)
__global__ __launch_bounds__(256, 1)
void gemm_qkv(const __nv_bfloat16* __restrict__ xh, const __nv_bfloat16* __restrict__ xl,
              const __nv_bfloat16* __restrict__ wh, const __nv_bfloat16* __restrict__ wl,
              const float* __restrict__ bq, const float* __restrict__ bk,
              const float* __restrict__ bv,
              const int* __restrict__ gather, const int* __restrict__ cnt,
              __nv_bfloat16* __restrict__ qh, __nv_bfloat16* __restrict__ ql,
              __nv_bfloat16* __restrict__ kh, __nv_bfloat16* __restrict__ kl,
              __nv_bfloat16* __restrict__ vh, __nv_bfloat16* __restrict__ vl)
{
    const int w = blockIdx.x >> 3;
    const int col0 = (blockIdx.x & 7) * BN;
    const int row0 = blockIdx.y * BM;
    const int NW = DIM * DIM;
    const float* bias = (w == 0) ? bq : (w == 1) ? bk : bv;
    __nv_bfloat16* Chi = (w == 0) ? qh : (w == 1) ? kh : vh;
    __nv_bfloat16* Clo = (w == 0) ? ql : (w == 1) ? kl : vl;
    const float scale = (w == 0) ? QK_SCALE : 1.0f;
    const int mode = (w == 0) ? 0 : 2;
    gemm_body(xh, xl, wh + (size_t)w * NW, wl + (size_t)w * NW, bias,
              nullptr, Chi, Clo, gather, cnt, mode, scale, row0, col0);
}

__global__ __launch_bounds__(256, 1)
void gemm_out(const __nv_bfloat16* __restrict__ oh, const __nv_bfloat16* __restrict__ ol,
              const __nv_bfloat16* __restrict__ wh, const __nv_bfloat16* __restrict__ wl,
              const float* __restrict__ bias, float* __restrict__ out)
{
    gemm_body(oh, ol, wh, wl, bias, out, nullptr, nullptr, nullptr, nullptr,
              1, 1.0f, blockIdx.y * BM, blockIdx.x * BN);
}

// ---------------------------------------------------------------------------
// MMA flash attention over compacted keys, dynamic tile count
// ---------------------------------------------------------------------------
#define AQ 128
#define AK 64
#define SM_QH 0
#define SM_QL 18432
#define SM_ST0 36864
#define ST_STRIDE 37120
#define OFF_KH 0
#define OFF_KL 9216
#define OFF_VH 18432
#define OFF_VL 27648
#define OFF_MSK 36864
#define A_NSTG 4
#define ATTN_SMEM (SM_ST0 + A_NSTG * ST_STRIDE)

__global__ __launch_bounds__(256, 1)
void attn_mma(const __nv_bfloat16* __restrict__ Qh_, const __nv_bfloat16* __restrict__ Ql_,
              const __nv_bfloat16* __restrict__ Kh_, const __nv_bfloat16* __restrict__ Kl_,
              const __nv_bfloat16* __restrict__ Vh_, const __nv_bfloat16* __restrict__ Vl_,
              const int* __restrict__ mc, const int* __restrict__ cntp,
              __nv_bfloat16* __restrict__ Oh_, __nv_bfloat16* __restrict__ Ol_)
{
    extern __shared__ char sm[];
    const uint32_t sb = smem_u32(sm);
    const int tid = threadIdx.x, lane = tid & 31, wid = tid >> 5;
    const int bh = blockIdx.y, b = bh >> 4, h = bh & 15;
    const int q0 = blockIdx.x * AQ;
    const size_t base = (size_t)bh * SEQ * HD;
    const int* mrow = mc + b * SEQ;
    const int nt = (cntp[b] + AK - 1) >> 6;

#define A_ISSUE(tile, stage) do { \
    uint32_t st_ = sb + SM_ST0 + (stage) * ST_STRIDE; \
    _Pragma("unroll") \
    for (int i_ = 0; i_ < 2; i_++) { \
        int idx_ = tid + i_ * 256, r_ = idx_ >> 3, c_ = idx_ & 7; \
        size_t go_ = base + (size_t)((tile) * AK + r_) * HD + c_ * 8; \
        uint32_t so_ = r_ * 144 + c_ * 16; \
        cpa16(st_ + OFF_KH + so_, Kh_ + go_); \
        cpa16(st_ + OFF_KL + so_, Kl_ + go_); \
        cpa16(st_ + OFF_VH + so_, Vh_ + go_); \
        cpa16(st_ + OFF_VL + so_, Vl_ + go_); \
    } \
    if (tid < 16) cpa16(st_ + OFF_MSK + tid * 16, mrow + (tile) * AK + tid * 4); \
    asm volatile("cp.async.commit_group;" ::: "memory"); \
} while (0)
#define A_EMPTY() asm volatile("cp.async.commit_group;" ::: "memory")

    {
#pragma unroll
        for (int i = 0; i < 4; i++) {
            int idx = tid + i * 256, r = idx >> 3, c = idx & 7;
            size_t go = base + (size_t)(q0 + r) * HD + c * 8;
            cpa16(sb + SM_QH + r * 144 + c * 16, Qh_ + go);
            cpa16(sb + SM_QL + r * 144 + c * 16, Ql_ + go);
        }
        A_ISSUE(0, 0);   // group 0 includes Q
    }
    if (nt > 1) A_ISSUE(1, 1); else A_EMPTY();
    if (nt > 2) A_ISSUE(2, 2); else A_EMPTY();

    asm volatile("cp.async.wait_group 2;" ::: "memory");
    __syncthreads();

    uint32_t qh[4][4], ql[4][4];
    {
        const int qrow = wid * 16 + (lane & 15);
        const int qc = (lane >> 4) * 8;
#pragma unroll
        for (int kf = 0; kf < 4; kf++) {
            uint32_t a = sb + SM_QH + qrow * 144 + (kf * 16 + qc) * 2;
            ldsm_x4(qh[kf], a);
            ldsm_x4(ql[kf], a + (SM_QL - SM_QH));
        }
    }

    float O[8][4];
#pragma unroll
    for (int i = 0; i < 8; i++)
#pragma unroll
        for (int j = 0; j < 4; j++) O[i][j] = 0.f;
    float mrun0 = -1e30f, mrun1 = -1e30f, lrun0 = 0.f, lrun1 = 0.f;

    const int kc2 = (lane & 3) * 2;
    const int krow = ((lane >> 4) & 1) * 8 + (lane & 7);
    const int kcol = ((lane >> 3) & 1) * 8;
    const int vrow = ((lane >> 3) & 1) * 8 + (lane & 7);
    const int vcol = ((lane >> 4) & 1) * 8;

    for (int t = 0; t < nt; t++) {
        const int stg = t & 3;
        if (t > 0) {
            asm volatile("cp.async.wait_group 2;" ::: "memory");
            __syncthreads();
        }
        if (t + 3 < nt) A_ISSUE(t + 3, (t + 3) & 3); else A_EMPTY();

        const uint32_t st = sb + SM_ST0 + stg * ST_STRIDE;
        const char* stc = sm + SM_ST0 + stg * ST_STRIDE;

        // ---- S = Qh*Kh + Qh*Kl + Ql*Kh ----
        float S[8][4];
#pragma unroll
        for (int i = 0; i < 8; i++)
#pragma unroll
            for (int j = 0; j < 4; j++) S[i][j] = 0.f;

#pragma unroll
        for (int kf = 0; kf < 4; kf++) {
            uint32_t kb[4][4], klr[4][4];
#pragma unroll
            for (int np = 0; np < 4; np++) {
                uint32_t a = st + OFF_KH + (np * 16 + krow) * 144 + (kf * 16 + kcol) * 2;
                ldsm_x4(kb[np], a);
                ldsm_x4(klr[np], a + (OFF_KL - OFF_KH));
            }
#pragma unroll
            for (int np = 0; np < 4; np++) {
                mma16816(S[2 * np],     qh[kf], &kb[np][0]);
                mma16816(S[2 * np],     qh[kf], &klr[np][0]);
                mma16816(S[2 * np],     ql[kf], &kb[np][0]);
                mma16816(S[2 * np + 1], qh[kf], &kb[np][2]);
                mma16816(S[2 * np + 1], qh[kf], &klr[np][2]);
                mma16816(S[2 * np + 1], ql[kf], &kb[np][2]);
            }
        }

        // ---- mask + online softmax ----
        float tmax0 = -1e30f, tmax1 = -1e30f;
#pragma unroll
        for (int nti = 0; nti < 8; nti++) {
            const int k = nti * 8 + kc2;
            const int m0 = *(const int*)(stc + OFF_MSK + k * 4);
            const int m1 = *(const int*)(stc + OFF_MSK + k * 4 + 4);
            if (m0) { S[nti][0] = -CUDART_INF_F; S[nti][2] = -CUDART_INF_F; }
            if (m1) { S[nti][1] = -CUDART_INF_F; S[nti][3] = -CUDART_INF_F; }
            tmax0 = fmaxf(tmax0, fmaxf(S[nti][0], S[nti][1]));
            tmax1 = fmaxf(tmax1, fmaxf(S[nti][2], S[nti][3]));
        }
        tmax0 = fmaxf(tmax0, __shfl_xor_sync(0xFFFFFFFF, tmax0, 1));
        tmax0 = fmaxf(tmax0, __shfl_xor_sync(0xFFFFFFFF, tmax0, 2));
        tmax1 = fmaxf(tmax1, __shfl_xor_sync(0xFFFFFFFF, tmax1, 1));
        tmax1 = fmaxf(tmax1, __shfl_xor_sync(0xFFFFFFFF, tmax1, 2));

        const float mn0 = fmaxf(mrun0, tmax0);
        const float mn1 = fmaxf(mrun1, tmax1);
        const float sc0 = __expf(mrun0 - mn0);
        const float sc1 = __expf(mrun1 - mn1);
        mrun0 = mn0; mrun1 = mn1;

        float ts0 = 0.f, ts1 = 0.f;
        uint32_t ph[8][2], pl[8][2];
#pragma unroll
        for (int nti = 0; nti < 8; nti++) {
            const float p0 = __expf(S[nti][0] - mn0);
            const float p1 = __expf(S[nti][1] - mn0);
            const float p2 = __expf(S[nti][2] - mn1);
            const float p3 = __expf(S[nti][3] - mn1);
            ts0 += p0 + p1; ts1 += p2 + p3;
            split_pack(p0, p1, ph[nti][0], pl[nti][0]);
            split_pack(p2, p3, ph[nti][1], pl[nti][1]);
        }
        ts0 += __shfl_xor_sync(0xFFFFFFFF, ts0, 1);
        ts0 += __shfl_xor_sync(0xFFFFFFFF, ts0, 2);
        ts1 += __shfl_xor_sync(0xFFFFFFFF, ts1, 1);
        ts1 += __shfl_xor_sync(0xFFFFFFFF, ts1, 2);
        lrun0 = lrun0 * sc0 + ts0;
        lrun1 = lrun1 * sc1 + ts1;
#pragma unroll
        for (int nti = 0; nti < 8; nti++) {
            O[nti][0] *= sc0; O[nti][1] *= sc0;
            O[nti][2] *= sc1; O[nti][3] *= sc1;
        }

        // ---- O += Ph*Vh + Ph*Vl + Pl*Vh ----
#pragma unroll
        for (int kf = 0; kf < 4; kf++) {
            uint32_t ah[4] = {ph[2 * kf][0], ph[2 * kf][1], ph[2 * kf + 1][0], ph[2 * kf + 1][1]};
            uint32_t al[4] = {pl[2 * kf][0], pl[2 * kf][1], pl[2 * kf + 1][0], pl[2 * kf + 1][1]};
            uint32_t vb[4][4], vlr[4][4];
#pragma unroll
            for (int np = 0; np < 4; np++) {
                uint32_t a = st + OFF_VH + (kf * 16 + vrow) * 144 + (np * 16 + vcol) * 2;
                ldsm_x4t(vb[np], a);
                ldsm_x4t(vlr[np], a + (OFF_VL - OFF_VH));
            }
#pragma unroll
            for (int np = 0; np < 4; np++) {
                mma16816(O[2 * np],     ah, &vb[np][0]);
                mma16816(O[2 * np],     ah, &vlr[np][0]);
                mma16816(O[2 * np],     al, &vb[np][0]);
                mma16816(O[2 * np + 1], ah, &vb[np][2]);
                mma16816(O[2 * np + 1], ah, &vlr[np][2]);
                mma16816(O[2 * np + 1], al, &vb[np][2]);
            }
        }
    }

    // ---- epilogue ----
    const float inv0 = 1.f / lrun0;
    const float inv1 = 1.f / lrun1;
    const int g = lane >> 2;
    const size_t row0 = (size_t)(b * SEQ + q0 + wid * 16 + g) * DIM + h * HD;
    const size_t row1 = row0 + (size_t)8 * DIM;
#pragma unroll
    for (int nti = 0; nti < 8; nti++) {
        const int col = nti * 8 + kc2;
        uint32_t hp, lp;
        split_pack(O[nti][0] * inv0, O[nti][1] * inv0, hp, lp);
        *(uint32_t*)&Oh_[row0 + col] = hp;
        *(uint32_t*)&Ol_[row0 + col] = lp;
        split_pack(O[nti][2] * inv1, O[nti][3] * inv1, hp, lp);
        *(uint32_t*)&Oh_[row1 + col] = hp;
        *(uint32_t*)&Ol_[row1 + col] = lp;
    }
}

// ---------------------------------------------------------------------------
// Launch
// ---------------------------------------------------------------------------
extern "C" void kernel_launch(void* const* d_in, const int* in_sizes, int n_in,
                              void* d_out, int out_size)
{
    const float* x  = (const float*)d_in[0];
    const int* mask = (const int*)d_in[1];
    const float* Wq = (const float*)d_in[2];
    const float* bq = (const float*)d_in[3];
    const float* Wk = (const float*)d_in[4];
    const float* bk = (const float*)d_in[5];
    const float* Wv = (const float*)d_in[6];
    const float* bv = (const float*)d_in[7];
    const float* Wo = (const float*)d_in[8];
    const float* bo = (const float*)d_in[9];
    float* out = (float*)d_out;

    __nv_bfloat16 *pqh, *pql, *pkh, *pkl, *pvh, *pvl;
    __nv_bfloat16 *pxh, *pxl, *pwh, *pwl, *poh, *pol;
    int *pgat, *pcnt, *pmc;
    cudaGetSymbolAddress((void**)&pqh, g_qh);
    cudaGetSymbolAddress((void**)&pql, g_ql);
    cudaGetSymbolAddress((void**)&pkh, g_kh);
    cudaGetSymbolAddress((void**)&pkl, g_kl);
    cudaGetSymbolAddress((void**)&pvh, g_vh);
    cudaGetSymbolAddress((void**)&pvl, g_vl);
    cudaGetSymbolAddress((void**)&pxh, g_xh);
    cudaGetSymbolAddress((void**)&pxl, g_xl);
    cudaGetSymbolAddress((void**)&pwh, g_wh);
    cudaGetSymbolAddress((void**)&pwl, g_wl);
    cudaGetSymbolAddress((void**)&poh, g_oh);
    cudaGetSymbolAddress((void**)&pol, g_ol);
    cudaGetSymbolAddress((void**)&pgat, g_gather);
    cudaGetSymbolAddress((void**)&pcnt, g_cnt);
    cudaGetSymbolAddress((void**)&pmc, g_mc);

    cudaFuncSetAttribute(gemm_qkv, cudaFuncAttributeMaxDynamicSharedMemorySize, GEMM_SMEM);
    cudaFuncSetAttribute(gemm_out, cudaFuncAttributeMaxDynamicSharedMemorySize, GEMM_SMEM);
    cudaFuncSetAttribute(attn_mma, cudaFuncAttributeMaxDynamicSharedMemorySize, ATTN_SMEM);

    const int NW = DIM * DIM;

    split_kernel<<<1024, 256>>>(x,  pxh, pxl, NROWS * DIM / 4);
    split_kernel<<<512, 256>>>(Wq, pwh + 0 * NW, pwl + 0 * NW, NW / 4);
    split_kernel<<<512, 256>>>(Wk, pwh + 1 * NW, pwl + 1 * NW, NW / 4);
    split_kernel<<<512, 256>>>(Wv, pwh + 2 * NW, pwl + 2 * NW, NW / 4);
    split_kernel<<<512, 256>>>(Wo, pwh + 3 * NW, pwl + 3 * NW, NW / 4);

    compact_kernel<<<BATCH, 256>>>(mask, pgat, pcnt, pmc);
    zeropad_kv<<<BATCH * HEADS, 256>>>(pkh, pkl, pvh, pvl, pcnt);

    dim3 qkvgrid(24, NROWS / BM);
    gemm_qkv<<<qkvgrid, 256, GEMM_SMEM>>>(pxh, pxl, pwh, pwl, bq, bk, bv,
                                          pgat, pcnt,
                                          pqh, pql, pkh, pkl, pvh, pvl);

    dim3 agrid(SEQ / AQ, BATCH * HEADS);
    attn_mma<<<agrid, 256, ATTN_SMEM>>>(pqh, pql, pkh, pkl, pvh, pvl, pmc, pcnt, poh, pol);

    dim3 ogrid(DIM / BN, NROWS / BM);
    gemm_out<<<ogrid, 256, GEMM_SMEM>>>(poh, pol, pwh + 3 * NW, pwl + 3 * NW, bo, out);
}

// round 9
// speedup vs baseline: 5.5575x; 1.2223x over previous
#include <cuda_runtime.h>
#include <cuda_bf16.h>
#include <cuda_fp16.h>
#include <math_constants.h>
#include <cstdint>

// Problem constants
#define BATCH 4
#define SEQ   2048
#define DIM   1024
#define HEADS 16
#define HD    64
#define NROWS (BATCH * SEQ)   // 8192
#define QK_SCALE 0.125f

__device__ __forceinline__ uint32_t smem_u32(const void* p) {
    uint32_t a;
    asm("{ .reg .u64 t; cvta.to.shared.u64 t, %1; cvt.u32.u64 %0, t; }" : "=r"(a) : "l"(p));
    return a;
}
// bf16 mma (attention)
__device__ __forceinline__ void mma16816(float* d, const uint32_t* a, const uint32_t* b) {
    asm volatile("mma.sync.aligned.m16n8k16.row.col.f32.bf16.bf16.f32 "
        "{%0,%1,%2,%3}, {%4,%5,%6,%7}, {%8,%9}, {%0,%1,%2,%3};"
        : "+f"(d[0]), "+f"(d[1]), "+f"(d[2]), "+f"(d[3])
        : "r"(a[0]), "r"(a[1]), "r"(a[2]), "r"(a[3]), "r"(b[0]), "r"(b[1]));
}
// fp16 mma (projections)
__device__ __forceinline__ void mma16816h(float* d, const uint32_t* a, const uint32_t* b) {
    asm volatile("mma.sync.aligned.m16n8k16.row.col.f32.f16.f16.f32 "
        "{%0,%1,%2,%3}, {%4,%5,%6,%7}, {%8,%9}, {%0,%1,%2,%3};"
        : "+f"(d[0]), "+f"(d[1]), "+f"(d[2]), "+f"(d[3])
        : "r"(a[0]), "r"(a[1]), "r"(a[2]), "r"(a[3]), "r"(b[0]), "r"(b[1]));
}
__device__ __forceinline__ void ldsm_x4(uint32_t* r, uint32_t addr) {
    asm volatile("ldmatrix.sync.aligned.m8n8.x4.shared.b16 {%0,%1,%2,%3}, [%4];"
        : "=r"(r[0]), "=r"(r[1]), "=r"(r[2]), "=r"(r[3]) : "r"(addr));
}
__device__ __forceinline__ void ldsm_x4t(uint32_t* r, uint32_t addr) {
    asm volatile("ldmatrix.sync.aligned.m8n8.x4.trans.shared.b16 {%0,%1,%2,%3}, [%4];"
        : "=r"(r[0]), "=r"(r[1]), "=r"(r[2]), "=r"(r[3]) : "r"(addr));
}
__device__ __forceinline__ void cpa16(uint32_t s, const void* g) {
    asm volatile("cp.async.cg.shared.global [%0], [%1], 16;" :: "r"(s), "l"(g));
}
// bf16 hi/lo pack (QKV epilogue -> attention inputs)
__device__ __forceinline__ void split_pack(float v0, float v1, uint32_t& hp, uint32_t& lp) {
    __nv_bfloat16 h0 = __float2bfloat16(v0), h1 = __float2bfloat16(v1);
    __nv_bfloat162 hh; hh.x = h0; hh.y = h1;
    hp = *reinterpret_cast<uint32_t*>(&hh);
    __nv_bfloat162 ll = __floats2bfloat162_rn(v0 - __bfloat162float(h0),
                                              v1 - __bfloat162float(h1));
    lp = *reinterpret_cast<uint32_t*>(&ll);
}
// fp16 hi/lo pack (attention epilogue -> out-proj inputs)
__device__ __forceinline__ void split_pack_h(float v0, float v1, uint32_t& hp, uint32_t& lp) {
    __half h0 = __float2half_rn(v0), h1 = __float2half_rn(v1);
    __half2 hh; hh.x = h0; hh.y = h1;
    hp = *reinterpret_cast<uint32_t*>(&hh);
    __half2 ll;
    ll.x = __float2half_rn(v0 - __half2float(h0));
    ll.y = __float2half_rn(v1 - __half2float(h1));
    lp = *reinterpret_cast<uint32_t*>(&ll);
}

// ---------------------------------------------------------------------------
// Scratch
// ---------------------------------------------------------------------------
#define QKV_ELEMS (BATCH * HEADS * SEQ * HD)
__device__ __nv_bfloat16 g_qh[QKV_ELEMS];
__device__ __nv_bfloat16 g_ql[QKV_ELEMS];
__device__ __nv_bfloat16 g_kh[QKV_ELEMS];   // compacted along S
__device__ __nv_bfloat16 g_kl[QKV_ELEMS];
__device__ __nv_bfloat16 g_vh[QKV_ELEMS];
__device__ __nv_bfloat16 g_vl[QKV_ELEMS];
__device__ __half g_xh[NROWS * DIM];        // fp16 hi/lo of x
__device__ __half g_xl[NROWS * DIM];
__device__ __half g_w16[4 * DIM * DIM];     // fp16-rounded weights
__device__ __half g_oh[NROWS * DIM];        // fp16 hi/lo of attn out
__device__ __half g_ol[NROWS * DIM];
__device__ int g_gather[BATCH * SEQ];
__device__ int g_cnt[BATCH];

// ---------------------------------------------------------------------------
// fp32 -> fp16 hi/lo split (x)
// ---------------------------------------------------------------------------
struct h4 { __half v[4]; };

__global__ void splitx_kernel(const float* __restrict__ src,
                              __half* __restrict__ hi,
                              __half* __restrict__ lo, int n4)
{
    for (int i = blockIdx.x * blockDim.x + threadIdx.x; i < n4; i += gridDim.x * blockDim.x) {
        float4 x = ((const float4*)src)[i];
        h4 h, l;
        float f[4] = {x.x, x.y, x.z, x.w};
#pragma unroll
        for (int j = 0; j < 4; j++) {
            __half hv = __float2half_rn(f[j]);
            h.v[j] = hv;
            l.v[j] = __float2half_rn(f[j] - __half2float(hv));
        }
        ((h4*)hi)[i] = h;
        ((h4*)lo)[i] = l;
    }
}

// fp32 -> fp16 round, all four weights in one launch
__global__ void roundw_kernel(const float* __restrict__ w0, const float* __restrict__ w1,
                              const float* __restrict__ w2, const float* __restrict__ w3,
                              __half* __restrict__ dst)
{
    const int n4w = (DIM * DIM) / 4;   // 262144
    for (int i = blockIdx.x * blockDim.x + threadIdx.x; i < 4 * n4w;
         i += gridDim.x * blockDim.x) {
        const int w = i / n4w;
        const int j = i - w * n4w;
        const float* s = (w == 0) ? w0 : (w == 1) ? w1 : (w == 2) ? w2 : w3;
        float4 x = ((const float4*)s)[j];
        h4 h;
        h.v[0] = __float2half_rn(x.x); h.v[1] = __float2half_rn(x.y);
        h.v[2] = __float2half_rn(x.z); h.v[3] = __float2half_rn(x.w);
        ((h4*)dst)[i] = h;
    }
}

// ---------------------------------------------------------------------------
// Mask compaction: stable scan; gather list + count.
// ---------------------------------------------------------------------------
__global__ __launch_bounds__(256)
void compact_kernel(const int* __restrict__ mask,
                    int* __restrict__ gather, int* __restrict__ cnt)
{
    __shared__ int cnts[256];
    __shared__ int offs[256];
    const int b = blockIdx.x;
    const int t = threadIdx.x;
    const int* m = mask + b * SEQ;

    int c = 0;
#pragma unroll
    for (int j = 0; j < 8; j++) c += (m[t * 8 + j] == 0);
    cnts[t] = c;
    __syncthreads();
    if (t == 0) {
        int run = 0;
        for (int i = 0; i < 256; i++) { offs[i] = run; run += cnts[i]; }
        cnt[b] = run;
    }
    __syncthreads();
    int o = offs[t];
#pragma unroll
    for (int j = 0; j < 8; j++) {
        const int s = t * 8 + j;
        if (m[s] == 0) { gather[b * SEQ + o] = s; o++; }
    }
}

// ---------------------------------------------------------------------------
// fp16 2-term GEMM (A = hi+lo fp16 exact, W = fp16 rounded), 4-stage pipeline
// mode 0: bf16 hi/lo scatter [B,H,S,HD] by s (Q)
// mode 2: A rows gathered; store at compacted row (K/V)
// mode 1: fp32 row-major
// ---------------------------------------------------------------------------
#define BM 128
#define BN 128
#define BK 32
#define NKC (DIM / BK)
#define TILE_SB (128 * 80)          // 10240 B (32 fp16 = 64 B + 16 pad per row)
#define STAGE_SB (3 * TILE_SB)      // 30720 B: A_hi, A_lo, W
#define NSTG 4
#define GEMM_SMEM (NSTG * STAGE_SB) // 122880 B

__device__ __forceinline__ void gemm_body(
    const __half* Ahi, const __half* Alo, const __half* W16,
    const float* bias, float* C,
    __nv_bfloat16* Chi, __nv_bfloat16* Clo,
    const int* gather, const int* cntp,
    int mode, float scale, int row0, int col0)
{
    extern __shared__ char smraw[];
    const uint32_t smem_base = smem_u32(smraw);

    const int tid = threadIdx.x;
    const int lane = tid & 31;
    const int wid = tid >> 5;
    const int wm = wid & 1;
    const int wn = wid >> 1;

    int cntb = 0;
    if (mode == 2) {
        const int b = row0 >> 11;
        cntb = cntp[b];
        if ((row0 & (SEQ - 1)) >= cntb) return;
    }

    float acc[4][4][4];
#pragma unroll
    for (int i = 0; i < 4; i++)
#pragma unroll
        for (int j = 0; j < 4; j++)
#pragma unroll
            for (int r = 0; r < 4; r++) acc[i][j][r] = 0.f;

    const int r0l = tid >> 2;
    const int cu  = tid & 3;

    const uint4* aptr[2][2];
    const uint4* wptr[2];
#pragma unroll
    for (int j = 0; j < 2; j++) {
        const int r = r0l + j * 64;
        int srcA;
        if (mode == 2) {
            const int n = row0 + r;
            const int b = n >> 11;
            int i = n & (SEQ - 1);
            if (i >= cntb) i = cntb - 1;
            srcA = (b << 11) + gather[(b << 11) + i];
        } else {
            srcA = row0 + r;
        }
        aptr[j][0] = (const uint4*)Ahi + (size_t)srcA * 128 + cu;
        aptr[j][1] = (const uint4*)Alo + (size_t)srcA * 128 + cu;
        wptr[j]    = (const uint4*)W16 + (size_t)(col0 + r) * 128 + cu;
    }

#define G_ISSUE(kc, buf) do { \
    uint32_t sb_ = smem_base + (buf) * STAGE_SB; \
    _Pragma("unroll") \
    for (int j_ = 0; j_ < 2; j_++) { \
        const int r_ = r0l + j_ * 64; \
        const uint32_t so_ = r_ * 80 + cu * 16; \
        cpa16(sb_ + 0 * TILE_SB + so_, aptr[j_][0] + (kc) * 4); \
        cpa16(sb_ + 1 * TILE_SB + so_, aptr[j_][1] + (kc) * 4); \
        cpa16(sb_ + 2 * TILE_SB + so_, wptr[j_] + (kc) * 4); \
    } \
    asm volatile("cp.async.commit_group;" ::: "memory"); \
} while (0)

    G_ISSUE(0, 0);
    G_ISSUE(1, 1);
    G_ISSUE(2, 2);

    for (int kc = 0; kc < NKC; kc++) {
        const int buf = kc & 3;
        asm volatile("cp.async.wait_group 2;" ::: "memory");
        __syncthreads();
        if (kc + 3 < NKC) G_ISSUE(kc + 3, (kc + 3) & 3);

        const uint32_t sb = smem_base + buf * STAGE_SB;
#pragma unroll
        for (int s = 0; s < 2; s++) {
            uint32_t a_h[4][4], a_l[4][4];
            const uint32_t acol = s * 32 + ((lane >> 4) << 4);
#pragma unroll
            for (int mt = 0; mt < 4; mt++) {
                const int r = wm * 64 + mt * 16 + (lane & 15);
                uint32_t addr = sb + r * 80 + acol;
                ldsm_x4(a_h[mt], addr);
                ldsm_x4(a_l[mt], addr + TILE_SB);
            }
            uint32_t wf[4][2];
            const int mat = lane >> 3;
            const int mr = lane & 7;
            const uint32_t bcol = s * 32 + ((mat & 1) << 4);
#pragma unroll
            for (int np = 0; np < 2; np++) {
                const int n = wn * 32 + (np * 2 + (mat >> 1)) * 8 + mr;
                uint32_t addr = sb + 2 * TILE_SB + n * 80 + bcol;
                uint32_t q[4];
                ldsm_x4(q, addr);
                wf[np * 2][0] = q[0]; wf[np * 2][1] = q[1];
                wf[np * 2 + 1][0] = q[2]; wf[np * 2 + 1][1] = q[3];
            }
#pragma unroll
            for (int mt = 0; mt < 4; mt++)
#pragma unroll
                for (int nt = 0; nt < 4; nt++) {
                    mma16816h(acc[mt][nt], a_h[mt], wf[nt]);
                    mma16816h(acc[mt][nt], a_l[mt], wf[nt]);
                }
        }
    }

    const int g = lane >> 2;
    const int tg2 = (lane & 3) * 2;
#pragma unroll
    for (int mt = 0; mt < 4; mt++) {
#pragma unroll
        for (int hh = 0; hh < 2; hh++) {
            const int n = row0 + wm * 64 + mt * 16 + g + hh * 8;
            if (mode == 1) {
#pragma unroll
                for (int nt = 0; nt < 4; nt++) {
                    const int m = col0 + wn * 32 + nt * 8 + tg2;
                    float2 w;
                    w.x = acc[mt][nt][hh * 2 + 0] + bias[m];
                    w.y = acc[mt][nt][hh * 2 + 1] + bias[m + 1];
                    *(float2*)&C[(size_t)n * DIM + m] = w;
                }
            } else {
                const int b = n >> 11;
                const int sq = n & (SEQ - 1);
                if (mode == 2 && sq >= cntb) continue;
#pragma unroll
                for (int nt = 0; nt < 4; nt++) {
                    const int m = col0 + wn * 32 + nt * 8 + tg2;
                    const float v0 = (acc[mt][nt][hh * 2 + 0] + bias[m]) * scale;
                    const float v1 = (acc[mt][nt][hh * 2 + 1] + bias[m + 1]) * scale;
                    const int h = m >> 6;
                    const int hd = m & (HD - 1);
                    uint32_t hp, lp;
                    split_pack(v0, v1, hp, lp);
                    const size_t o = (((size_t)(b * HEADS + h) * SEQ) + sq) * HD + hd;
                    *(uint32_t*)&Chi[o] = hp;
                    *(uint32_t*)&Clo[o] = lp;
                }
            }
        }
    }
}

// Fused Q/K/V projection: grid (24, 64)
__global__ __launch_bounds__(256, 1)
void gemm_qkv(const __half* __restrict__ xh, const __half* __restrict__ xl,
              const __half* __restrict__ w16,
              const float* __restrict__ bq, const float* __restrict__ bk,
              const float* __restrict__ bv,
              const int* __restrict__ gather, const int* __restrict__ cnt,
              __nv_bfloat16* __restrict__ qh, __nv_bfloat16* __restrict__ ql,
              __nv_bfloat16* __restrict__ kh, __nv_bfloat16* __restrict__ kl,
              __nv_bfloat16* __restrict__ vh, __nv_bfloat16* __restrict__ vl)
{
    const int w = blockIdx.x >> 3;
    const int col0 = (blockIdx.x & 7) * BN;
    const int row0 = blockIdx.y * BM;
    const int NW = DIM * DIM;
    const float* bias = (w == 0) ? bq : (w == 1) ? bk : bv;
    __nv_bfloat16* Chi = (w == 0) ? qh : (w == 1) ? kh : vh;
    __nv_bfloat16* Clo = (w == 0) ? ql : (w == 1) ? kl : vl;
    const float scale = (w == 0) ? QK_SCALE : 1.0f;
    const int mode = (w == 0) ? 0 : 2;
    gemm_body(xh, xl, w16 + (size_t)w * NW, bias,
              nullptr, Chi, Clo, gather, cnt, mode, scale, row0, col0);
}

__global__ __launch_bounds__(256, 1)
void gemm_out(const __half* __restrict__ oh, const __half* __restrict__ ol,
              const __half* __restrict__ w16,
              const float* __restrict__ bias, float* __restrict__ out)
{
    gemm_body(oh, ol, w16, bias, out, nullptr, nullptr, nullptr, nullptr,
              1, 1.0f, blockIdx.y * BM, blockIdx.x * BN);
}

// ---------------------------------------------------------------------------
// MMA flash attention (bf16x3) over compacted keys; mask by key index vs cnt
// ---------------------------------------------------------------------------
#define AQ 128
#define AK 64
#define SM_QH 0
#define SM_QL 18432
#define SM_ST0 36864
#define ST_STRIDE 36864
#define OFF_KH 0
#define OFF_KL 9216
#define OFF_VH 18432
#define OFF_VL 27648
#define A_NSTG 4
#define ATTN_SMEM (SM_ST0 + A_NSTG * ST_STRIDE)   // 184320

__global__ __launch_bounds__(256, 1)
void attn_mma(const __nv_bfloat16* __restrict__ Qh_, const __nv_bfloat16* __restrict__ Ql_,
              const __nv_bfloat16* __restrict__ Kh_, const __nv_bfloat16* __restrict__ Kl_,
              const __nv_bfloat16* __restrict__ Vh_, const __nv_bfloat16* __restrict__ Vl_,
              const int* __restrict__ cntp,
              __half* __restrict__ Oh_, __half* __restrict__ Ol_)
{
    extern __shared__ char sm[];
    const uint32_t sb = smem_u32(sm);
    const int tid = threadIdx.x, lane = tid & 31, wid = tid >> 5;
    const int bh = blockIdx.y, b = bh >> 4, h = bh & 15;
    const int q0 = blockIdx.x * AQ;
    const size_t base = (size_t)bh * SEQ * HD;
    const int cntb = cntp[b];
    const int nt = (cntb + AK - 1) >> 6;

#define A_ISSUE(tile, stage) do { \
    uint32_t st_ = sb + SM_ST0 + (stage) * ST_STRIDE; \
    _Pragma("unroll") \
    for (int i_ = 0; i_ < 2; i_++) { \
        int idx_ = tid + i_ * 256, r_ = idx_ >> 3, c_ = idx_ & 7; \
        size_t go_ = base + (size_t)((tile) * AK + r_) * HD + c_ * 8; \
        uint32_t so_ = r_ * 144 + c_ * 16; \
        cpa16(st_ + OFF_KH + so_, Kh_ + go_); \
        cpa16(st_ + OFF_KL + so_, Kl_ + go_); \
        cpa16(st_ + OFF_VH + so_, Vh_ + go_); \
        cpa16(st_ + OFF_VL + so_, Vl_ + go_); \
    } \
    asm volatile("cp.async.commit_group;" ::: "memory"); \
} while (0)
#define A_EMPTY() asm volatile("cp.async.commit_group;" ::: "memory")

    {
#pragma unroll
        for (int i = 0; i < 4; i++) {
            int idx = tid + i * 256, r = idx >> 3, c = idx & 7;
            size_t go = base + (size_t)(q0 + r) * HD + c * 8;
            cpa16(sb + SM_QH + r * 144 + c * 16, Qh_ + go);
            cpa16(sb + SM_QL + r * 144 + c * 16, Ql_ + go);
        }
        A_ISSUE(0, 0);   // group 0 includes Q
    }
    if (nt > 1) A_ISSUE(1, 1); else A_EMPTY();
    if (nt > 2) A_ISSUE(2, 2); else A_EMPTY();

    asm volatile("cp.async.wait_group 2;" ::: "memory");
    __syncthreads();

    uint32_t qh[4][4], ql[4][4];
    {
        const int qrow = wid * 16 + (lane & 15);
        const int qc = (lane >> 4) * 8;
#pragma unroll
        for (int kf = 0; kf < 4; kf++) {
            uint32_t a = sb + SM_QH + qrow * 144 + (kf * 16 + qc) * 2;
            ldsm_x4(qh[kf], a);
            ldsm_x4(ql[kf], a + (SM_QL - SM_QH));
        }
    }

    float O[8][4];
#pragma unroll
    for (int i = 0; i < 8; i++)
#pragma unroll
        for (int j = 0; j < 4; j++) O[i][j] = 0.f;
    float mrun0 = -1e30f, mrun1 = -1e30f, lrun0 = 0.f, lrun1 = 0.f;

    const int kc2 = (lane & 3) * 2;
    const int krow = ((lane >> 4) & 1) * 8 + (lane & 7);
    const int kcol = ((lane >> 3) & 1) * 8;
    const int vrow = ((lane >> 3) & 1) * 8 + (lane & 7);
    const int vcol = ((lane >> 4) & 1) * 8;

    for (int t = 0; t < nt; t++) {
        const int stg = t & 3;
        if (t > 0) {
            asm volatile("cp.async.wait_group 2;" ::: "memory");
            __syncthreads();
        }
        if (t + 3 < nt) A_ISSUE(t + 3, (t + 3) & 3); else A_EMPTY();

        const uint32_t st = sb + SM_ST0 + stg * ST_STRIDE;
        const int limit = cntb - t * AK;   // keys >= limit in this tile are pad

        // ---- S = Qh*Kh + Qh*Kl + Ql*Kh ----
        float S[8][4];
#pragma unroll
        for (int i = 0; i < 8; i++)
#pragma unroll
            for (int j = 0; j < 4; j++) S[i][j] = 0.f;

#pragma unroll
        for (int kf = 0; kf < 4; kf++) {
            uint32_t kb[4][4], klr[4][4];
#pragma unroll
            for (int np = 0; np < 4; np++) {
                uint32_t a = st + OFF_KH + (np * 16 + krow) * 144 + (kf * 16 + kcol) * 2;
                ldsm_x4(kb[np], a);
                ldsm_x4(klr[np], a + (OFF_KL - OFF_KH));
            }
#pragma unroll
            for (int np = 0; np < 4; np++) {
                mma16816(S[2 * np],     qh[kf], &kb[np][0]);
                mma16816(S[2 * np],     qh[kf], &klr[np][0]);
                mma16816(S[2 * np],     ql[kf], &kb[np][0]);
                mma16816(S[2 * np + 1], qh[kf], &kb[np][2]);
                mma16816(S[2 * np + 1], qh[kf], &klr[np][2]);
                mma16816(S[2 * np + 1], ql[kf], &kb[np][2]);
            }
        }

        // ---- pad mask (index-based) + online softmax ----
        float tmax0 = -1e30f, tmax1 = -1e30f;
#pragma unroll
        for (int nti = 0; nti < 8; nti++) {
            const int k = nti * 8 + kc2;
            if (k >= limit)     { S[nti][0] = -CUDART_INF_F; S[nti][2] = -CUDART_INF_F; }
            if (k + 1 >= limit) { S[nti][1] = -CUDART_INF_F; S[nti][3] = -CUDART_INF_F; }
            tmax0 = fmaxf(tmax0, fmaxf(S[nti][0], S[nti][1]));
            tmax1 = fmaxf(tmax1, fmaxf(S[nti][2], S[nti][3]));
        }
        tmax0 = fmaxf(tmax0, __shfl_xor_sync(0xFFFFFFFF, tmax0, 1));
        tmax0 = fmaxf(tmax0, __shfl_xor_sync(0xFFFFFFFF, tmax0, 2));
        tmax1 = fmaxf(tmax1, __shfl_xor_sync(0xFFFFFFFF, tmax1, 1));
        tmax1 = fmaxf(tmax1, __shfl_xor_sync(0xFFFFFFFF, tmax1, 2));

        const float mn0 = fmaxf(mrun0, tmax0);
        const float mn1 = fmaxf(mrun1, tmax1);
        const float sc0 = __expf(mrun0 - mn0);
        const float sc1 = __expf(mrun1 - mn1);
        mrun0 = mn0; mrun1 = mn1;

        float ts0 = 0.f, ts1 = 0.f;
        uint32_t ph[8][2], pl[8][2];
#pragma unroll
        for (int nti = 0; nti < 8; nti++) {
            const float p0 = __expf(S[nti][0] - mn0);
            const float p1 = __expf(S[nti][1] - mn0);
            const float p2 = __expf(S[nti][2] - mn1);
            const float p3 = __expf(S[nti][3] - mn1);
            ts0 += p0 + p1; ts1 += p2 + p3;
            split_pack(p0, p1, ph[nti][0], pl[nti][0]);
            split_pack(p2, p3, ph[nti][1], pl[nti][1]);
        }
        ts0 += __shfl_xor_sync(0xFFFFFFFF, ts0, 1);
        ts0 += __shfl_xor_sync(0xFFFFFFFF, ts0, 2);
        ts1 += __shfl_xor_sync(0xFFFFFFFF, ts1, 1);
        ts1 += __shfl_xor_sync(0xFFFFFFFF, ts1, 2);
        lrun0 = lrun0 * sc0 + ts0;
        lrun1 = lrun1 * sc1 + ts1;
#pragma unroll
        for (int nti = 0; nti < 8; nti++) {
            O[nti][0] *= sc0; O[nti][1] *= sc0;
            O[nti][2] *= sc1; O[nti][3] *= sc1;
        }

        // ---- O += Ph*Vh + Ph*Vl + Pl*Vh ----
#pragma unroll
        for (int kf = 0; kf < 4; kf++) {
            uint32_t ah[4] = {ph[2 * kf][0], ph[2 * kf][1], ph[2 * kf + 1][0], ph[2 * kf + 1][1]};
            uint32_t al[4] = {pl[2 * kf][0], pl[2 * kf][1], pl[2 * kf + 1][0], pl[2 * kf + 1][1]};
            uint32_t vb[4][4], vlr[4][4];
#pragma unroll
            for (int np = 0; np < 4; np++) {
                uint32_t a = st + OFF_VH + (kf * 16 + vrow) * 144 + (np * 16 + vcol) * 2;
                ldsm_x4t(vb[np], a);
                ldsm_x4t(vlr[np], a + (OFF_VL - OFF_VH));
            }
#pragma unroll
            for (int np = 0; np < 4; np++) {
                mma16816(O[2 * np],     ah, &vb[np][0]);
                mma16816(O[2 * np],     ah, &vlr[np][0]);
                mma16816(O[2 * np],     al, &vb[np][0]);
                mma16816(O[2 * np + 1], ah, &vb[np][2]);
                mma16816(O[2 * np + 1], ah, &vlr[np][2]);
                mma16816(O[2 * np + 1], al, &vb[np][2]);
            }
        }
    }

    // ---- epilogue: fp16 hi/lo ----
    const float inv0 = 1.f / lrun0;
    const float inv1 = 1.f / lrun1;
    const int g = lane >> 2;
    const size_t row0 = (size_t)(b * SEQ + q0 + wid * 16 + g) * DIM + h * HD;
    const size_t row1 = row0 + (size_t)8 * DIM;
#pragma unroll
    for (int nti = 0; nti < 8; nti++) {
        const int col = nti * 8 + kc2;
        uint32_t hp, lp;
        split_pack_h(O[nti][0] * inv0, O[nti][1] * inv0, hp, lp);
        *(uint32_t*)&Oh_[row0 + col] = hp;
        *(uint32_t*)&Ol_[row0 + col] = lp;
        split_pack_h(O[nti][2] * inv1, O[nti][3] * inv1, hp, lp);
        *(uint32_t*)&Oh_[row1 + col] = hp;
        *(uint32_t*)&Ol_[row1 + col] = lp;
    }
}

// ---------------------------------------------------------------------------
// Launch
// ---------------------------------------------------------------------------
extern "C" void kernel_launch(void* const* d_in, const int* in_sizes, int n_in,
                              void* d_out, int out_size)
{
    const float* x  = (const float*)d_in[0];
    const int* mask = (const int*)d_in[1];
    const float* Wq = (const float*)d_in[2];
    const float* bq = (const float*)d_in[3];
    const float* Wk = (const float*)d_in[4];
    const float* bk = (const float*)d_in[5];
    const float* Wv = (const float*)d_in[6];
    const float* bv = (const float*)d_in[7];
    const float* Wo = (const float*)d_in[8];
    const float* bo = (const float*)d_in[9];
    float* out = (float*)d_out;

    __nv_bfloat16 *pqh, *pql, *pkh, *pkl, *pvh, *pvl;
    __half *pxh, *pxl, *pw16, *poh, *pol;
    int *pgat, *pcnt;
    cudaGetSymbolAddress((void**)&pqh, g_qh);
    cudaGetSymbolAddress((void**)&pql, g_ql);
    cudaGetSymbolAddress((void**)&pkh, g_kh);
    cudaGetSymbolAddress((void**)&pkl, g_kl);
    cudaGetSymbolAddress((void**)&pvh, g_vh);
    cudaGetSymbolAddress((void**)&pvl, g_vl);
    cudaGetSymbolAddress((void**)&pxh, g_xh);
    cudaGetSymbolAddress((void**)&pxl, g_xl);
    cudaGetSymbolAddress((void**)&pw16, g_w16);
    cudaGetSymbolAddress((void**)&poh, g_oh);
    cudaGetSymbolAddress((void**)&pol, g_ol);
    cudaGetSymbolAddress((void**)&pgat, g_gather);
    cudaGetSymbolAddress((void**)&pcnt, g_cnt);

    cudaFuncSetAttribute(gemm_qkv, cudaFuncAttributeMaxDynamicSharedMemorySize, GEMM_SMEM);
    cudaFuncSetAttribute(gemm_out, cudaFuncAttributeMaxDynamicSharedMemorySize, GEMM_SMEM);
    cudaFuncSetAttribute(attn_mma, cudaFuncAttributeMaxDynamicSharedMemorySize, ATTN_SMEM);

    splitx_kernel<<<1024, 256>>>(x, pxh, pxl, NROWS * DIM / 4);
    roundw_kernel<<<1024, 256>>>(Wq, Wk, Wv, Wo, pw16);
    compact_kernel<<<BATCH, 256>>>(mask, pgat, pcnt);

    dim3 qkvgrid(24, NROWS / BM);
    gemm_qkv<<<qkvgrid, 256, GEMM_SMEM>>>(pxh, pxl, pw16, bq, bk, bv,
                                          pgat, pcnt,
                                          pqh, pql, pkh, pkl, pvh, pvl);

    dim3 agrid(SEQ / AQ, BATCH * HEADS);
    attn_mma<<<agrid, 256, ATTN_SMEM>>>(pqh, pql, pkh, pkl, pvh, pvl, pcnt, poh, pol);

    dim3 ogrid(DIM / BN, NROWS / BM);
    gemm_out<<<ogrid, 256, GEMM_SMEM>>>(poh, pol, pw16 + 3 * (size_t)DIM * DIM, bo, out);
}